// round 1
// baseline (speedup 1.0000x reference)
#include <cuda_runtime.h>
#include <cuda_bf16.h>
#include <cstdint>

#define N_TOTAL 2048
#define S_STEPS 32
#define DIM 256
#define PER_TS 1050688      // >= 1025*1025, 16B-aligned element count
#define UV_STRIDE 2049

// ---------------- scratch (device globals; no dynamic allocation) ------------
__device__ float d_M[(size_t)S_STEPS * PER_TS];     // padded Mt per timestep
__device__ float d_K[(size_t)S_STEPS * PER_TS];     // padded K per timestep
__device__ float d_Xg[(size_t)S_STEPS * N_TOTAL * DIM]; // gathered rows per ts
__device__ float d_norm[S_STEPS * N_TOTAL];
__device__ int   d_it[N_TOTAL], d_ic[N_TOTAL];
__device__ int   d_nt, d_nc;
__device__ float d_p;
__device__ float d_lam[S_STEPS], d_delta[S_STEPS];
__device__ float d_u[S_STEPS * UV_STRIDE];
__device__ float d_z[S_STEPS * UV_STRIDE];
__device__ float d_pmax[S_STEPS * 256];
__device__ float d_psum[S_STEPS * 256];
__device__ float d_pfin[S_STEPS * 257];

// ---------------- fast exp (Cephes, FMA pipe; args here are in [-8, 0]) ------
__device__ __forceinline__ float fexpf_(float x) {
    float z = fmaf(x, 1.4426950408889634f, 12582912.0f);
    float n = z - 12582912.0f;                      // round-to-nearest integer
    float r = fmaf(n, -0.693359375f, x);
    r = fmaf(n, 2.12194440e-4f, r);
    float p = 1.9875691500e-4f;
    p = fmaf(p, r, 1.3981999507e-3f);
    p = fmaf(p, r, 8.3334519073e-3f);
    p = fmaf(p, r, 4.1665795894e-2f);
    p = fmaf(p, r, 1.6666665459e-1f);
    p = fmaf(p, r, 5.0000001201e-1f);
    float e = fmaf(r * r, p, r) + 1.0f;
    int ni = (int)n;
    return __int_as_float(__float_as_int(e) + (ni << 23));
}

// ---------------- 1) partition indices (deterministic, single block) ---------
__global__ void part_kernel(const int* __restrict__ t) {
    __shared__ int wcntT[64];
    __shared__ int wprefT[64], wprefC[64];
    int tid = threadIdx.x, lane = tid & 31, wid = tid >> 5;
    for (int c = wid; c < 64; c += 32) {
        int e = c * 32 + lane;
        int f = t[e] > 0;
        unsigned m = __ballot_sync(0xffffffffu, f);
        if (lane == 0) wcntT[c] = __popc(m);
    }
    __syncthreads();
    if (tid == 0) {
        int aT = 0;
        for (int c = 0; c < 64; c++) {
            wprefT[c] = aT;
            wprefC[c] = c * 32 - aT;
            aT += wcntT[c];
        }
        d_nt = aT;
        d_nc = N_TOTAL - aT;
        d_p  = (float)aT / (float)N_TOTAL;
    }
    __syncthreads();
    for (int c = wid; c < 64; c += 32) {
        int e = c * 32 + lane;
        int f = t[e] > 0;
        unsigned m  = __ballot_sync(0xffffffffu, f);
        unsigned lt = ((1u << lane) - 1u);
        if (f) d_it[wprefT[c] + __popc(m & lt)]   = e;
        else   d_ic[wprefC[c] + __popc(~m & lt)]  = e;
    }
}

// ---------------- 2) gather rows + row norms ---------------------------------
// grid (N_TOTAL, S), 64 threads
__global__ void gather_kernel(const float* __restrict__ enc) {
    int r = blockIdx.x, s = blockIdx.y, tid = threadIdx.x;
    int nt = d_nt;
    int src = (r < nt) ? d_it[r] : d_ic[r - nt];
    const float4* in = (const float4*)(enc + ((size_t)src * S_STEPS + s) * DIM);
    float4* out = (float4*)(d_Xg + ((size_t)s * N_TOTAL + r) * DIM);
    float4 v = in[tid];
    out[tid] = v;
    float nrm = v.x * v.x + v.y * v.y + v.z * v.z + v.w * v.w;
    for (int o = 16; o; o >>= 1) nrm += __shfl_down_sync(0xffffffffu, nrm, o);
    __shared__ float sn[2];
    if ((tid & 31) == 0) sn[tid >> 5] = nrm;
    __syncthreads();
    if (tid == 0) d_norm[s * N_TOTAL + r] = sn[0] + sn[1];
}

// ---------------- 3) M = ||xi||^2 + ||yj||^2 - 2 xi.yj (128x128x8 SGEMM) -----
// grid (16,16,S), 256 threads
__global__ void gemm_kernel() {
    __shared__ float As[8][132];
    __shared__ float Bs[8][132];
    __shared__ float rbuf[256];

    int s = blockIdx.z;
    int nt = d_nt, nc = d_nc;
    int i0 = blockIdx.y * 128, j0 = blockIdx.x * 128;
    int tid = threadIdx.x;
    int pidx = s * 256 + blockIdx.y * 16 + blockIdx.x;

    if (i0 >= nt || j0 >= nc) {
        if (tid == 0) { d_pmax[pidx] = 0.0f; d_psum[pidx] = 0.0f; }
        return;
    }

    int lr = tid >> 1;
    int lk = (tid & 1) * 4;
    int ty = tid >> 4, tx = tid & 15;
    const float* Xb = d_Xg + (size_t)s * N_TOTAL * DIM;

    float acc[64];
#pragma unroll
    for (int q = 0; q < 64; q++) acc[q] = 0.0f;

    for (int kt = 0; kt < DIM / 8; kt++) {
        int k0 = kt * 8;
        float4 av = make_float4(0.f, 0.f, 0.f, 0.f);
        float4 bv = make_float4(0.f, 0.f, 0.f, 0.f);
        if (i0 + lr < nt) av = *(const float4*)(Xb + (size_t)(i0 + lr) * DIM + k0 + lk);
        if (j0 + lr < nc) bv = *(const float4*)(Xb + (size_t)(nt + j0 + lr) * DIM + k0 + lk);
        __syncthreads();
        As[lk + 0][lr] = av.x; As[lk + 1][lr] = av.y;
        As[lk + 2][lr] = av.z; As[lk + 3][lr] = av.w;
        Bs[lk + 0][lr] = bv.x; Bs[lk + 1][lr] = bv.y;
        Bs[lk + 2][lr] = bv.z; Bs[lk + 3][lr] = bv.w;
        __syncthreads();
#pragma unroll
        for (int kk = 0; kk < 8; kk++) {
            float a_[8], b_[8];
            *(float4*)&a_[0] = *(const float4*)&As[kk][ty * 4];
            *(float4*)&a_[4] = *(const float4*)&As[kk][64 + ty * 4];
            *(float4*)&b_[0] = *(const float4*)&Bs[kk][tx * 4];
            *(float4*)&b_[4] = *(const float4*)&Bs[kk][64 + tx * 4];
#pragma unroll
            for (int uu = 0; uu < 8; uu++)
#pragma unroll
                for (int vv = 0; vv < 8; vv++)
                    acc[uu * 8 + vv] = fmaf(a_[uu], b_[vv], acc[uu * 8 + vv]);
        }
    }

    // epilogue: M + per-block max/sum partials
    int ncp = nc + 1;
    float* Mb = d_M + (size_t)s * PER_TS;
    float lmax = 0.0f, lsum = 0.0f;
#pragma unroll
    for (int uu = 0; uu < 8; uu++) {
        int gi = i0 + ((uu < 4) ? (ty * 4 + uu) : (64 + ty * 4 + uu - 4));
        if (gi >= nt) continue;
        float na = d_norm[s * N_TOTAL + gi];
#pragma unroll
        for (int vv = 0; vv < 8; vv++) {
            int gj = j0 + ((vv < 4) ? (tx * 4 + vv) : (64 + tx * 4 + vv - 4));
            if (gj >= nc) continue;
            float nb = d_norm[s * N_TOTAL + nt + gj];
            float m = na + nb - 2.0f * acc[uu * 8 + vv];
            Mb[(size_t)gi * ncp + gj] = m;
            lmax = fmaxf(lmax, m);
            lsum += m;
        }
    }
    rbuf[tid] = lmax; __syncthreads();
    for (int st = 128; st; st >>= 1) {
        if (tid < st) rbuf[tid] = fmaxf(rbuf[tid], rbuf[tid + st]);
        __syncthreads();
    }
    if (tid == 0) d_pmax[pidx] = rbuf[0];
    __syncthreads();
    rbuf[tid] = lsum; __syncthreads();
    for (int st = 128; st; st >>= 1) {
        if (tid < st) rbuf[tid] += rbuf[tid + st];
        __syncthreads();
    }
    if (tid == 0) d_psum[pidx] = rbuf[0];
}

// ---------------- 4) per-timestep stats: delta = max(M), lam = 1/mean(M) -----
// grid (S), 256 threads
__global__ void reduce_stats() {
    __shared__ float rb[256];
    int s = blockIdx.x, tid = threadIdx.x;
    float mv = d_pmax[s * 256 + tid];
    float sv = d_psum[s * 256 + tid];
    rb[tid] = mv; __syncthreads();
    for (int st = 128; st; st >>= 1) {
        if (tid < st) rb[tid] = fmaxf(rb[tid], rb[tid + st]);
        __syncthreads();
    }
    float mx = rb[0];
    __syncthreads();
    rb[tid] = sv; __syncthreads();
    for (int st = 128; st; st >>= 1) {
        if (tid < st) rb[tid] += rb[tid + st];
        __syncthreads();
    }
    if (tid == 0) {
        d_delta[s] = mx;
        d_lam[s] = ((float)d_nt * (float)d_nc) / rb[0];  // LAM=1
    }
}

// ---------------- 5) K = exp(-lam*Mt)+1e-6, write pads into M too ------------
// grid (2049, S), 256 threads; one block per padded row
__global__ void expk_kernel() {
    int s = blockIdx.y, r = blockIdx.x;
    int nt = d_nt, nc = d_nc, ncp = nc + 1;
    if (r > nt) return;
    float lam = d_lam[s], delta = d_delta[s];
    float* Mb = d_M + (size_t)s * PER_TS + (size_t)r * ncp;
    float* Kb = d_K + (size_t)s * PER_TS + (size_t)r * ncp;
    for (int c = threadIdx.x; c <= nc; c += 256) {
        float m;
        if (r < nt && c < nc) {
            m = Mb[c];
        } else if (r == nt && c == nc) {
            m = 0.0f; Mb[c] = 0.0f;
        } else {
            m = delta; Mb[c] = delta;
        }
        Kb[c] = fexpf_(-lam * m) + 1e-6f;
    }
}

// ---------------- 6) u = a ---------------------------------------------------
// grid (9, S), 256 threads
__global__ void init_u() {
    int s = blockIdx.y;
    int i = blockIdx.x * 256 + threadIdx.x;
    int nt = d_nt;
    if (i > nt) return;
    float p = d_p;
    d_u[s * UV_STRIDE + i] = (i < nt) ? (p / (float)nt) : (1.0f - p);
}

// ---------------- 7) z = b / (K^T u) (also produces v on the final call) -----
// grid (65, S), 256 threads: 32 columns/block, 8 warps split rows
__global__ void colpass() {
    int s = blockIdx.y;
    int nt = d_nt, nc = d_nc, ntp = nt + 1, ncp = nc + 1;
    int lane = threadIdx.x & 31, wid = threadIdx.x >> 5;
    int j = blockIdx.x * 32 + lane;
    bool valid = (j < ncp);
    const float* Kb = d_K + (size_t)s * PER_TS;
    const float* ub = d_u + s * UV_STRIDE;
    float acc = 0.0f;
    if (valid) {
        int i = wid;
        for (; i + 24 < ntp; i += 32) {
            float u0 = ub[i], u1 = ub[i + 8], u2 = ub[i + 16], u3 = ub[i + 24];
            float k0 = Kb[(size_t)i * ncp + j];
            float k1 = Kb[(size_t)(i + 8) * ncp + j];
            float k2 = Kb[(size_t)(i + 16) * ncp + j];
            float k3 = Kb[(size_t)(i + 24) * ncp + j];
            acc = fmaf(k0, u0, acc);
            acc = fmaf(k1, u1, acc);
            acc = fmaf(k2, u2, acc);
            acc = fmaf(k3, u3, acc);
        }
        for (; i < ntp; i += 8)
            acc = fmaf(Kb[(size_t)i * ncp + j], ub[i], acc);
    }
    __shared__ float red[8][33];
    red[wid][lane] = acc;
    __syncthreads();
    if (wid == 0 && valid) {
        float t = red[0][lane];
#pragma unroll
        for (int w = 1; w < 8; w++) t += red[w][lane];
        float p = d_p;
        float bj = (j < nc) ? ((1.0f - p) / (float)nc) : p;
        d_z[s * UV_STRIDE + j] = bj / t;
    }
}

// ---------------- 8) u = a / (K z) -------------------------------------------
// grid (257, S), 256 threads: warp per row
__global__ void rowpass() {
    int s = blockIdx.y;
    int nt = d_nt, nc = d_nc, ntp = nt + 1, ncp = nc + 1;
    int lane = threadIdx.x & 31, wid = threadIdx.x >> 5;
    int i = blockIdx.x * 8 + wid;
    if (i >= ntp) return;
    const float* Kr = d_K + (size_t)s * PER_TS + (size_t)i * ncp;
    const float* zb = d_z + s * UV_STRIDE;
    float acc = 0.0f;
    int j = lane;
    for (; j + 96 < ncp; j += 128) {
        acc = fmaf(Kr[j],      zb[j],      acc);
        acc = fmaf(Kr[j + 32], zb[j + 32], acc);
        acc = fmaf(Kr[j + 64], zb[j + 64], acc);
        acc = fmaf(Kr[j + 96], zb[j + 96], acc);
    }
    for (; j < ncp; j += 32) acc = fmaf(Kr[j], zb[j], acc);
    for (int o = 16; o; o >>= 1) acc += __shfl_down_sync(0xffffffffu, acc, o);
    if (lane == 0) {
        float p = d_p;
        float ai = (i < nt) ? (p / (float)nt) : (1.0f - p);
        d_u[s * UV_STRIDE + i] = ai / acc;
    }
}

// ---------------- 9) partial of sum_ij u_i K_ij v_j Mt_ij --------------------
// grid (257, S), 256 threads
__global__ void finalsum() {
    int s = blockIdx.y;
    int nt = d_nt, nc = d_nc, ntp = nt + 1, ncp = nc + 1;
    int lane = threadIdx.x & 31, wid = threadIdx.x >> 5;
    int i = blockIdx.x * 8 + wid;
    float acc = 0.0f;
    if (i < ntp) {
        const float* Kr = d_K + (size_t)s * PER_TS + (size_t)i * ncp;
        const float* Mr = d_M + (size_t)s * PER_TS + (size_t)i * ncp;
        const float* vb = d_z + s * UV_STRIDE;
        float ui = d_u[s * UV_STRIDE + i];
        for (int j = lane; j < ncp; j += 32)
            acc += Kr[j] * Mr[j] * vb[j];
        acc *= ui;
    }
    for (int o = 16; o; o >>= 1) acc += __shfl_down_sync(0xffffffffu, acc, o);
    __shared__ float wsum[8];
    if (lane == 0) wsum[wid] = acc;
    __syncthreads();
    if (threadIdx.x == 0) {
        float t = 0.0f;
#pragma unroll
        for (int w = 0; w < 8; w++) t += wsum[w];
        d_pfin[s * 257 + blockIdx.x] = t;
    }
}

// ---------------- 10) final deterministic reduce -----------------------------
__global__ void finalreduce(float* __restrict__ out) {
    __shared__ float rb[256];
    int tid = threadIdx.x;
    float a = 0.0f;
    for (int idx = tid; idx < S_STEPS * 257; idx += 256) a += d_pfin[idx];
    rb[tid] = a; __syncthreads();
    for (int st = 128; st; st >>= 1) {
        if (tid < st) rb[tid] += rb[tid + st];
        __syncthreads();
    }
    if (tid == 0) out[0] = 2.0f * rb[0];
}

// ---------------- launch -----------------------------------------------------
extern "C" void kernel_launch(void* const* d_in, const int* in_sizes, int n_in,
                              void* d_out, int out_size) {
    const float* enc = (const float*)d_in[0];
    const int*   t   = (const int*)d_in[2];
    float* out = (float*)d_out;

    part_kernel<<<1, 1024>>>(t);
    gather_kernel<<<dim3(N_TOTAL, S_STEPS), 64>>>(enc);
    gemm_kernel<<<dim3(16, 16, S_STEPS), 256>>>();
    reduce_stats<<<S_STEPS, 256>>>();
    expk_kernel<<<dim3(2049, S_STEPS), 256>>>();
    init_u<<<dim3(9, S_STEPS), 256>>>();
    for (int it = 0; it < 20; it++) {
        colpass<<<dim3(65, S_STEPS), 256>>>();
        rowpass<<<dim3(257, S_STEPS), 256>>>();
    }
    colpass<<<dim3(65, S_STEPS), 256>>>();   // v = b / (K^T u_final)
    finalsum<<<dim3(257, S_STEPS), 256>>>();
    finalreduce<<<1, 256>>>(out);
}

// round 5
// speedup vs baseline: 1.5880x; 1.5880x over previous
#include <cuda_runtime.h>
#include <cuda_fp16.h>
#include <cuda_bf16.h>
#include <cstdint>

#define N_TOTAL 2048
#define S_STEPS 32
#define DIM 256
#define PER_TS 1060864      // >= max over splits of (nt+1)*rs, rs=(nc+8)&~7
#define ZSTRIDE 2056

// ---------------- scratch (device globals; no dynamic allocation) ------------
__device__ __align__(16) __half d_Kh[(size_t)S_STEPS * PER_TS];
__device__ __align__(16) __half d_Mh[(size_t)S_STEPS * PER_TS];
__device__ __align__(16) __nv_bfloat16 d_Xhi[(size_t)S_STEPS * N_TOTAL * DIM];
__device__ __align__(16) __nv_bfloat16 d_Xlo[(size_t)S_STEPS * N_TOTAL * DIM];
__device__ float d_norm[S_STEPS * N_TOTAL];
__device__ int   d_it[N_TOTAL], d_ic[N_TOTAL];
__device__ int   d_nt, d_nc;
__device__ float d_p;
__device__ float d_lam[S_STEPS], d_delta[S_STEPS];
__device__ float d_u[S_STEPS * ZSTRIDE];
__device__ float d_z[S_STEPS * ZSTRIDE];
__device__ float d_pmax[S_STEPS * 256];
__device__ float d_psum[S_STEPS * 256];
__device__ float d_pfin[S_STEPS * 257];

// ---------------- fast exp (Cephes, FMA pipe; args in [-8, 0]) ---------------
__device__ __forceinline__ float fexpf_(float x) {
    float z = fmaf(x, 1.4426950408889634f, 12582912.0f);
    float n = z - 12582912.0f;
    float r = fmaf(n, -0.693359375f, x);
    r = fmaf(n, 2.12194440e-4f, r);
    float p = 1.9875691500e-4f;
    p = fmaf(p, r, 1.3981999507e-3f);
    p = fmaf(p, r, 8.3334519073e-3f);
    p = fmaf(p, r, 4.1665795894e-2f);
    p = fmaf(p, r, 1.6666665459e-1f);
    p = fmaf(p, r, 5.0000001201e-1f);
    float e = fmaf(r * r, p, r) + 1.0f;
    int ni = (int)n;
    return __int_as_float(__float_as_int(e) + (ni << 23));
}

__device__ __forceinline__ uint32_t smem_u32(const void* p) {
    uint32_t a;
    asm("{ .reg .u64 t; cvta.to.shared.u64 t, %1; cvt.u32.u64 %0, t; }" : "=r"(a) : "l"(p));
    return a;
}

#define LDSM4(R, addr) \
    asm volatile("ldmatrix.sync.aligned.m8n8.x4.shared.b16 {%0,%1,%2,%3}, [%4];" \
        : "=r"((R)[0]), "=r"((R)[1]), "=r"((R)[2]), "=r"((R)[3]) : "r"(addr))

#define MMA_BF16(C, A, b0_, b1_) \
    asm volatile("mma.sync.aligned.m16n8k16.row.col.f32.bf16.bf16.f32 " \
        "{%0,%1,%2,%3}, {%4,%5,%6,%7}, {%8,%9}, {%0,%1,%2,%3};" \
        : "+f"((C)[0]), "+f"((C)[1]), "+f"((C)[2]), "+f"((C)[3]) \
        : "r"((A)[0]), "r"((A)[1]), "r"((A)[2]), "r"((A)[3]), "r"(b0_), "r"(b1_))

// ---------------- 1) partition indices (deterministic, single block) ---------
__global__ void part_kernel(const int* __restrict__ t) {
    __shared__ int wcntT[64];
    __shared__ int wprefT[64], wprefC[64];
    int tid = threadIdx.x, lane = tid & 31, wid = tid >> 5;
    for (int c = wid; c < 64; c += 32) {
        int e = c * 32 + lane;
        int f = t[e] > 0;
        unsigned m = __ballot_sync(0xffffffffu, f);
        if (lane == 0) wcntT[c] = __popc(m);
    }
    __syncthreads();
    if (tid == 0) {
        int aT = 0;
        for (int c = 0; c < 64; c++) {
            wprefT[c] = aT;
            wprefC[c] = c * 32 - aT;
            aT += wcntT[c];
        }
        d_nt = aT;
        d_nc = N_TOTAL - aT;
        d_p  = (float)aT / (float)N_TOTAL;
    }
    __syncthreads();
    for (int c = wid; c < 64; c += 32) {
        int e = c * 32 + lane;
        int f = t[e] > 0;
        unsigned m  = __ballot_sync(0xffffffffu, f);
        unsigned lt = ((1u << lane) - 1u);
        if (f) d_it[wprefT[c] + __popc(m & lt)]  = e;
        else   d_ic[wprefC[c] + __popc(~m & lt)] = e;
    }
}

// ---------------- 2) gather rows -> bf16 hi/lo + fp32 row norms --------------
// grid (N_TOTAL, S), 64 threads
__global__ void gather_kernel(const float* __restrict__ enc) {
    int r = blockIdx.x, s = blockIdx.y, tid = threadIdx.x;
    int nt = d_nt;
    int src = (r < nt) ? d_it[r] : d_ic[r - nt];
    const float4* in = (const float4*)(enc + ((size_t)src * S_STEPS + s) * DIM);
    float4 v = in[tid];

    __nv_bfloat16 hx = __float2bfloat16_rn(v.x);
    __nv_bfloat16 hy = __float2bfloat16_rn(v.y);
    __nv_bfloat16 hz = __float2bfloat16_rn(v.z);
    __nv_bfloat16 hw = __float2bfloat16_rn(v.w);
    __nv_bfloat16 lx = __float2bfloat16_rn(v.x - __bfloat162float(hx));
    __nv_bfloat16 ly = __float2bfloat16_rn(v.y - __bfloat162float(hy));
    __nv_bfloat16 lz = __float2bfloat16_rn(v.z - __bfloat162float(hz));
    __nv_bfloat16 lw = __float2bfloat16_rn(v.w - __bfloat162float(hw));

    size_t base = ((size_t)s * N_TOTAL + r) * DIM + (size_t)tid * 4;
    __nv_bfloat162 h01 = {hx, hy}, h23 = {hz, hw};
    __nv_bfloat162 l01 = {lx, ly}, l23 = {lz, lw};
    uint2 hv = { *(unsigned*)&h01, *(unsigned*)&h23 };
    uint2 lv = { *(unsigned*)&l01, *(unsigned*)&l23 };
    *(uint2*)(d_Xhi + base) = hv;
    *(uint2*)(d_Xlo + base) = lv;

    float nrm = v.x * v.x + v.y * v.y + v.z * v.z + v.w * v.w;
    for (int o = 16; o; o >>= 1) nrm += __shfl_down_sync(0xffffffffu, nrm, o);
    __shared__ float sn[2];
    if ((tid & 31) == 0) sn[tid >> 5] = nrm;
    __syncthreads();
    if (tid == 0) d_norm[s * N_TOTAL + r] = sn[0] + sn[1];
}

// ---------------- 3) mma.sync bf16 GEMM: CTA 128x128, warps 64x32 ------------
// grid (16,16,S), 256 threads (8 warps: 2 m x 4 n)
__global__ void __launch_bounds__(256, 1) gemm_kernel() {
    __shared__ __align__(16) unsigned char sm[41984];
    const int AHI = 0, ALO = 10240, BHI = 20480, BLO = 30720;
    float* rbuf = (float*)(sm + 40960);

    int tid = threadIdx.x, lane = tid & 31, wid = tid >> 5;
    int wm = wid >> 2, wn = wid & 3;
    int s = blockIdx.z;
    int nt = d_nt, nc = d_nc;
    int i0 = blockIdx.y * 128, j0 = blockIdx.x * 128;
    int pidx = s * 256 + blockIdx.y * 16 + blockIdx.x;

    if (i0 >= nt || j0 >= nc) {
        if (tid == 0) { d_pmax[pidx] = 0.0f; d_psum[pidx] = 0.0f; }
        return;
    }

    uint32_t sb = smem_u32(sm);
    size_t Xbase = (size_t)s * N_TOTAL * DIM;
    const uint4 z4 = make_uint4(0, 0, 0, 0);

    float c[4][4][4];
#pragma unroll
    for (int a = 0; a < 4; a++)
#pragma unroll
        for (int b = 0; b < 4; b++)
#pragma unroll
            for (int q = 0; q < 4; q++) c[a][b][q] = 0.0f;

    for (int chunk = 0; chunk < 8; chunk++) {
        int k0 = chunk * 32;
#pragma unroll
        for (int h = 0; h < 2; h++) {
            int idx = tid + h * 256;
            int row = idx >> 2, seg = idx & 3;
            uint32_t doff = (uint32_t)row * 80 + (uint32_t)seg * 16;
            size_t asrc = Xbase + (size_t)(i0 + row) * DIM + k0 + seg * 8;
            size_t bsrc = Xbase + (size_t)(nt + j0 + row) * DIM + k0 + seg * 8;
            bool va = (i0 + row) < nt;
            bool vb = (j0 + row) < nc;
            uint4 ah = va ? *(const uint4*)(d_Xhi + asrc) : z4;
            uint4 al = va ? *(const uint4*)(d_Xlo + asrc) : z4;
            uint4 bh = vb ? *(const uint4*)(d_Xhi + bsrc) : z4;
            uint4 bl = vb ? *(const uint4*)(d_Xlo + bsrc) : z4;
            *(uint4*)(sm + AHI + doff) = ah;
            *(uint4*)(sm + ALO + doff) = al;
            *(uint4*)(sm + BHI + doff) = bh;
            *(uint4*)(sm + BLO + doff) = bl;
        }
        __syncthreads();

#pragma unroll
        for (int ks = 0; ks < 32; ks += 16) {
            uint32_t colb = (uint32_t)(ks + ((lane >> 4) << 3)) * 2;
            uint32_t ah[4][4], al[4][4], bhf[2][4], blf[2][4];
#pragma unroll
            for (int mt = 0; mt < 4; mt++) {
                uint32_t addr = sb + AHI + (uint32_t)(wm * 64 + mt * 16 + (lane & 15)) * 80 + colb;
                LDSM4(ah[mt], addr);
                LDSM4(al[mt], addr + (ALO - AHI));
            }
#pragma unroll
            for (int p = 0; p < 2; p++) {
                uint32_t addr = sb + BHI + (uint32_t)(wn * 32 + p * 16 + (lane & 15)) * 80 + colb;
                LDSM4(bhf[p], addr);
                LDSM4(blf[p], addr + (BLO - BHI));
            }
#pragma unroll
            for (int mt = 0; mt < 4; mt++)
#pragma unroll
                for (int nn = 0; nn < 4; nn++) {
                    int p = nn >> 1, od = nn & 1;
                    MMA_BF16(c[mt][nn], ah[mt], bhf[p][od], bhf[p][2 + od]);
                    MMA_BF16(c[mt][nn], ah[mt], blf[p][od], blf[p][2 + od]);
                    MMA_BF16(c[mt][nn], al[mt], bhf[p][od], bhf[p][2 + od]);
                }
        }
        __syncthreads();
    }

    // stage nb norms in smem (reuse A region)
    float* nbs = (float*)(sm + AHI);
    for (int q = tid; q < 128; q += 256)
        nbs[q] = (j0 + q < nc) ? d_norm[s * N_TOTAL + nt + j0 + q] : 0.0f;
    __syncthreads();

    int rs = (nc + 8) & ~7;
    float lmax = 0.0f, lsum = 0.0f;
#pragma unroll
    for (int mt = 0; mt < 4; mt++) {
        int gi0 = i0 + wm * 64 + mt * 16 + (lane >> 2);
        int gi1 = gi0 + 8;
        float na0 = (gi0 < nt) ? d_norm[s * N_TOTAL + gi0] : 0.0f;
        float na1 = (gi1 < nt) ? d_norm[s * N_TOTAL + gi1] : 0.0f;
#pragma unroll
        for (int nn = 0; nn < 4; nn++) {
            int lj = wn * 32 + nn * 8 + (lane & 3) * 2;
            int gj = j0 + lj;
            float nb0 = nbs[lj], nb1 = nbs[lj + 1];
            bool vj0 = gj < nc, vj1 = (gj + 1) < nc;
            float m00 = na0 + nb0 - 2.0f * c[mt][nn][0];
            float m01 = na0 + nb1 - 2.0f * c[mt][nn][1];
            float m10 = na1 + nb0 - 2.0f * c[mt][nn][2];
            float m11 = na1 + nb1 - 2.0f * c[mt][nn][3];
            if (gi0 < nt) {
                __half* Mr = d_Mh + (size_t)s * PER_TS + (size_t)gi0 * rs + gj;
                if (vj0) { lmax = fmaxf(lmax, m00); lsum += m00; }
                if (vj1) { lmax = fmaxf(lmax, m01); lsum += m01; }
                if (vj0 && vj1) *(__half2*)Mr = __floats2half2_rn(m00, m01);
                else if (vj0)   *Mr = __float2half_rn(m00);
            }
            if (gi1 < nt) {
                __half* Mr = d_Mh + (size_t)s * PER_TS + (size_t)gi1 * rs + gj;
                if (vj0) { lmax = fmaxf(lmax, m10); lsum += m10; }
                if (vj1) { lmax = fmaxf(lmax, m11); lsum += m11; }
                if (vj0 && vj1) *(__half2*)Mr = __floats2half2_rn(m10, m11);
                else if (vj0)   *Mr = __float2half_rn(m10);
            }
        }
    }

    rbuf[tid] = lmax; __syncthreads();
    for (int st = 128; st; st >>= 1) {
        if (tid < st) rbuf[tid] = fmaxf(rbuf[tid], rbuf[tid + st]);
        __syncthreads();
    }
    if (tid == 0) d_pmax[pidx] = rbuf[0];
    __syncthreads();
    rbuf[tid] = lsum; __syncthreads();
    for (int st = 128; st; st >>= 1) {
        if (tid < st) rbuf[tid] += rbuf[tid + st];
        __syncthreads();
    }
    if (tid == 0) d_psum[pidx] = rbuf[0];
}

// ---------------- 4) per-timestep stats --------------------------------------
// grid (S), 256 threads
__global__ void reduce_stats() {
    __shared__ float rb[256];
    int s = blockIdx.x, tid = threadIdx.x;
    float mv = d_pmax[s * 256 + tid];
    float sv = d_psum[s * 256 + tid];
    rb[tid] = mv; __syncthreads();
    for (int st = 128; st; st >>= 1) {
        if (tid < st) rb[tid] = fmaxf(rb[tid], rb[tid + st]);
        __syncthreads();
    }
    float mx = rb[0];
    __syncthreads();
    rb[tid] = sv; __syncthreads();
    for (int st = 128; st; st >>= 1) {
        if (tid < st) rb[tid] += rb[tid + st];
        __syncthreads();
    }
    if (tid == 0) {
        d_delta[s] = mx;
        d_lam[s] = ((float)d_nt * (float)d_nc) / rb[0];
    }
}

// ---------------- 5) K = fp16(exp(-lam*Mt)+1e-6), write pads -----------------
// grid (2049, S), 256 threads
__global__ void expk_kernel() {
    int s = blockIdx.y, r = blockIdx.x;
    int nt = d_nt, nc = d_nc, ncp = nc + 1;
    int rs = (ncp + 7) & ~7;
    if (r > nt) return;
    float lam = d_lam[s], delta = d_delta[s];
    __half* Mb = d_Mh + (size_t)s * PER_TS + (size_t)r * rs;
    __half* Kb = d_Kh + (size_t)s * PER_TS + (size_t)r * rs;
    for (int c = threadIdx.x; c < rs; c += 256) {
        if (c >= ncp) { Kb[c] = __float2half_rn(0.0f); Mb[c] = __float2half_rn(0.0f); continue; }
        float m;
        if (r < nt && c < nc) {
            m = __half2float(Mb[c]);
        } else if (r == nt && c == nc) {
            m = 0.0f; Mb[c] = __float2half_rn(0.0f);
        } else {
            m = delta; Mb[c] = __float2half_rn(delta);
        }
        Kb[c] = __float2half_rn(fexpf_(-lam * m) + 1e-6f);
    }
}

// ---------------- 6) u = a ---------------------------------------------------
// grid (9, S), 256 threads
__global__ void init_u() {
    int s = blockIdx.y;
    int i = blockIdx.x * 256 + threadIdx.x;
    int nt = d_nt;
    if (i > nt) return;
    float p = d_p;
    d_u[s * ZSTRIDE + i] = (i < nt) ? (p / (float)nt) : (1.0f - p);
}

// ---------------- 7) z = b / (K^T u) -----------------------------------------
// grid (33, S), 256 threads: 64 cols/block via half2, 8 warps split rows
__global__ void colpass() {
    int s = blockIdx.y;
    int nt = d_nt, nc = d_nc, ntp = nt + 1, ncp = nc + 1;
    int rs = (ncp + 7) & ~7;
    int lane = threadIdx.x & 31, wid = threadIdx.x >> 5;
    int j0 = blockIdx.x * 64;
    if (j0 >= rs) return;
    int jj = j0 + lane * 2;
    bool act = jj < rs;
    const __half* Kb = d_Kh + (size_t)s * PER_TS;
    const float* ub = d_u + s * ZSTRIDE;
    float a0 = 0.0f, a1 = 0.0f;
    if (act) {
        int i = wid;
        for (; i + 24 < ntp; i += 32) {
            float u0 = ub[i], u1 = ub[i + 8], u2 = ub[i + 16], u3 = ub[i + 24];
            __half2 k0 = *(const __half2*)(Kb + (size_t)i * rs + jj);
            __half2 k1 = *(const __half2*)(Kb + (size_t)(i + 8) * rs + jj);
            __half2 k2 = *(const __half2*)(Kb + (size_t)(i + 16) * rs + jj);
            __half2 k3 = *(const __half2*)(Kb + (size_t)(i + 24) * rs + jj);
            float2 f0 = __half22float2(k0), f1 = __half22float2(k1);
            float2 f2 = __half22float2(k2), f3 = __half22float2(k3);
            a0 = fmaf(f0.x, u0, a0); a1 = fmaf(f0.y, u0, a1);
            a0 = fmaf(f1.x, u1, a0); a1 = fmaf(f1.y, u1, a1);
            a0 = fmaf(f2.x, u2, a0); a1 = fmaf(f2.y, u2, a1);
            a0 = fmaf(f3.x, u3, a0); a1 = fmaf(f3.y, u3, a1);
        }
        for (; i < ntp; i += 8) {
            float u0 = ub[i];
            float2 f0 = __half22float2(*(const __half2*)(Kb + (size_t)i * rs + jj));
            a0 = fmaf(f0.x, u0, a0); a1 = fmaf(f0.y, u0, a1);
        }
    }
    __shared__ float red[8][64];
    red[wid][lane * 2] = a0;
    red[wid][lane * 2 + 1] = a1;
    __syncthreads();
    if (wid == 0) {
        float t0 = 0.0f, t1 = 0.0f;
#pragma unroll
        for (int w = 0; w < 8; w++) { t0 += red[w][lane * 2]; t1 += red[w][lane * 2 + 1]; }
        float p = d_p;
        float* zb = d_z + s * ZSTRIDE;
        int ja = j0 + lane * 2, jb = ja + 1;
        if (ja < rs) zb[ja] = (ja < nc) ? (((1.0f - p) / (float)nc) / t0)
                                        : ((ja == nc) ? (p / t0) : 0.0f);
        if (jb < rs) zb[jb] = (jb < nc) ? (((1.0f - p) / (float)nc) / t1)
                                        : ((jb == nc) ? (p / t1) : 0.0f);
    }
}

// ---------------- 8) u = a / (K z) -------------------------------------------
// grid (257, S), 256 threads: warp per row, half2
__global__ void rowpass() {
    int s = blockIdx.y;
    int nt = d_nt, nc = d_nc, ntp = nt + 1, ncp = nc + 1;
    int rs = (ncp + 7) & ~7;
    int lane = threadIdx.x & 31, wid = threadIdx.x >> 5;
    int i = blockIdx.x * 8 + wid;
    if (i >= ntp) return;
    const __half* Kr = d_Kh + (size_t)s * PER_TS + (size_t)i * rs;
    const float2* zb2 = (const float2*)(d_z + s * ZSTRIDE);
    float acc = 0.0f;
#pragma unroll 4
    for (int jj = lane * 2; jj < rs; jj += 64) {
        float2 kf = __half22float2(*(const __half2*)(Kr + jj));
        float2 zv = zb2[jj >> 1];
        acc = fmaf(kf.x, zv.x, fmaf(kf.y, zv.y, acc));
    }
    for (int o = 16; o; o >>= 1) acc += __shfl_down_sync(0xffffffffu, acc, o);
    if (lane == 0) {
        float p = d_p;
        float ai = (i < nt) ? (p / (float)nt) : (1.0f - p);
        d_u[s * ZSTRIDE + i] = ai / acc;
    }
}

// ---------------- 9) partials of sum_ij u_i K_ij v_j Mt_ij -------------------
// grid (257, S), 256 threads
__global__ void finalsum() {
    int s = blockIdx.y;
    int nt = d_nt, nc = d_nc, ntp = nt + 1, ncp = nc + 1;
    int rs = (ncp + 7) & ~7;
    int lane = threadIdx.x & 31, wid = threadIdx.x >> 5;
    int i = blockIdx.x * 8 + wid;
    float acc = 0.0f;
    if (i < ntp) {
        const __half* Kr = d_Kh + (size_t)s * PER_TS + (size_t)i * rs;
        const __half* Mr = d_Mh + (size_t)s * PER_TS + (size_t)i * rs;
        const float2* zb2 = (const float2*)(d_z + s * ZSTRIDE);
        float ui = d_u[s * ZSTRIDE + i];
        for (int jj = lane * 2; jj < rs; jj += 64) {
            float2 kf = __half22float2(*(const __half2*)(Kr + jj));
            float2 mf = __half22float2(*(const __half2*)(Mr + jj));
            float2 zv = zb2[jj >> 1];
            acc = fmaf(kf.x * mf.x, zv.x, fmaf(kf.y * mf.y, zv.y, acc));
        }
        acc *= ui;
    }
    for (int o = 16; o; o >>= 1) acc += __shfl_down_sync(0xffffffffu, acc, o);
    __shared__ float wsum[8];
    if (lane == 0) wsum[wid] = acc;
    __syncthreads();
    if (threadIdx.x == 0) {
        float tt = 0.0f;
#pragma unroll
        for (int w = 0; w < 8; w++) tt += wsum[w];
        d_pfin[s * 257 + blockIdx.x] = tt;
    }
}

// ---------------- 10) final deterministic reduce -----------------------------
__global__ void finalreduce(float* __restrict__ out) {
    __shared__ float rb[256];
    int tid = threadIdx.x;
    float a = 0.0f;
    for (int idx = tid; idx < S_STEPS * 257; idx += 256) a += d_pfin[idx];
    rb[tid] = a; __syncthreads();
    for (int st = 128; st; st >>= 1) {
        if (tid < st) rb[tid] += rb[tid + st];
        __syncthreads();
    }
    if (tid == 0) out[0] = 2.0f * rb[0];
}

// ---------------- launch -----------------------------------------------------
extern "C" void kernel_launch(void* const* d_in, const int* in_sizes, int n_in,
                              void* d_out, int out_size) {
    const float* enc = (const float*)d_in[0];
    const int*   t   = (const int*)d_in[2];
    float* out = (float*)d_out;

    part_kernel<<<1, 1024>>>(t);
    gather_kernel<<<dim3(N_TOTAL, S_STEPS), 64>>>(enc);
    gemm_kernel<<<dim3(16, 16, S_STEPS), 256>>>();
    reduce_stats<<<S_STEPS, 256>>>();
    expk_kernel<<<dim3(2049, S_STEPS), 256>>>();
    init_u<<<dim3(9, S_STEPS), 256>>>();
    for (int it = 0; it < 20; it++) {
        colpass<<<dim3(33, S_STEPS), 256>>>();
        rowpass<<<dim3(257, S_STEPS), 256>>>();
    }
    colpass<<<dim3(33, S_STEPS), 256>>>();   // v = b / (K^T u_final)
    finalsum<<<dim3(257, S_STEPS), 256>>>();
    finalreduce<<<1, 256>>>(out);
}

// round 7
// speedup vs baseline: 2.1337x; 1.3436x over previous
#include <cuda_runtime.h>
#include <cuda_fp16.h>
#include <cuda_bf16.h>
#include <cstdint>

#define N_TOTAL 2048
#define S_STEPS 32
#define DIM 256
#define PER_TS 1507328      // >= rows_max(1205) * rsU_max(1216)
#define ZSTRIDE 2056

// ---------------- scratch (device globals; no dynamic allocation) ------------
__device__ __align__(16) __half d_Mh[(size_t)S_STEPS * PER_TS];
__device__ __align__(16) __half d_Kh[(size_t)S_STEPS * PER_TS];
__device__ __align__(16) __nv_bfloat16 d_Xhi[(size_t)S_STEPS * N_TOTAL * DIM];
__device__ float d_norm[S_STEPS * N_TOTAL];
__device__ int   d_it[N_TOTAL], d_ic[N_TOTAL];
__device__ int   d_nt, d_nc;
__device__ float d_p;
__device__ float d_lam[S_STEPS], d_delta[S_STEPS];
__device__ __align__(16) float d_u[S_STEPS * ZSTRIDE];
__device__ __align__(16) float d_z[S_STEPS * ZSTRIDE];
__device__ float d_pmax[S_STEPS * 256];
__device__ float d_psum[S_STEPS * 256];
__device__ float d_pfin[256];

// ---------------- fast exp (Cephes, FMA pipe; args in [-8, 0]) ---------------
__device__ __forceinline__ float fexpf_(float x) {
    float z = fmaf(x, 1.4426950408889634f, 12582912.0f);
    float n = z - 12582912.0f;
    float r = fmaf(n, -0.693359375f, x);
    r = fmaf(n, 2.12194440e-4f, r);
    float p = 1.9875691500e-4f;
    p = fmaf(p, r, 1.3981999507e-3f);
    p = fmaf(p, r, 8.3334519073e-3f);
    p = fmaf(p, r, 4.1665795894e-2f);
    p = fmaf(p, r, 1.6666665459e-1f);
    p = fmaf(p, r, 5.0000001201e-1f);
    float e = fmaf(r * r, p, r) + 1.0f;
    int ni = (int)n;
    return __int_as_float(__float_as_int(e) + (ni << 23));
}

__device__ __forceinline__ uint32_t smem_u32(const void* p) {
    uint32_t a;
    asm("{ .reg .u64 t; cvta.to.shared.u64 t, %1; cvt.u32.u64 %0, t; }" : "=r"(a) : "l"(p));
    return a;
}

// 4 halves -> float4
__device__ __forceinline__ float4 h4_f4(uint2 w) {
    float2 a = __half22float2(*reinterpret_cast<__half2*>(&w.x));
    float2 b = __half22float2(*reinterpret_cast<__half2*>(&w.y));
    return make_float4(a.x, a.y, b.x, b.y);
}

#define CLUSTER_SYNC() do { \
    asm volatile("barrier.cluster.arrive.aligned;" ::: "memory"); \
    asm volatile("barrier.cluster.wait.aligned;" ::: "memory"); } while (0)

#define LDSM4(R, addr) \
    asm volatile("ldmatrix.sync.aligned.m8n8.x4.shared.b16 {%0,%1,%2,%3}, [%4];" \
        : "=r"((R)[0]), "=r"((R)[1]), "=r"((R)[2]), "=r"((R)[3]) : "r"(addr))

#define MMA_BF16(C, A, b0_, b1_) \
    asm volatile("mma.sync.aligned.m16n8k16.row.col.f32.bf16.bf16.f32 " \
        "{%0,%1,%2,%3}, {%4,%5,%6,%7}, {%8,%9}, {%0,%1,%2,%3};" \
        : "+f"((C)[0]), "+f"((C)[1]), "+f"((C)[2]), "+f"((C)[3]) \
        : "r"((A)[0]), "r"((A)[1]), "r"((A)[2]), "r"((A)[3]), "r"(b0_), "r"(b1_))

// ---------------- 1) partition indices (deterministic, single block) ---------
__global__ void part_kernel(const int* __restrict__ t) {
    __shared__ int wcntT[64];
    __shared__ int wprefT[64], wprefC[64];
    int tid = threadIdx.x, lane = tid & 31, wid = tid >> 5;
    for (int c = wid; c < 64; c += 32) {
        int e = c * 32 + lane;
        int f = t[e] > 0;
        unsigned m = __ballot_sync(0xffffffffu, f);
        if (lane == 0) wcntT[c] = __popc(m);
    }
    __syncthreads();
    if (tid == 0) {
        int aT = 0;
        for (int c = 0; c < 64; c++) {
            wprefT[c] = aT;
            wprefC[c] = c * 32 - aT;
            aT += wcntT[c];
        }
        d_nt = aT;
        d_nc = N_TOTAL - aT;
        d_p  = (float)aT / (float)N_TOTAL;
    }
    __syncthreads();
    for (int c = wid; c < 64; c += 32) {
        int e = c * 32 + lane;
        int f = t[e] > 0;
        unsigned m  = __ballot_sync(0xffffffffu, f);
        unsigned lt = ((1u << lane) - 1u);
        if (f) d_it[wprefT[c] + __popc(m & lt)]  = e;
        else   d_ic[wprefC[c] + __popc(~m & lt)] = e;
    }
}

// ---------------- 2) gather rows -> bf16 + fp32 row norms --------------------
// grid (N_TOTAL, S), 64 threads
__global__ void gather_kernel(const float* __restrict__ enc) {
    int r = blockIdx.x, s = blockIdx.y, tid = threadIdx.x;
    int nt = d_nt;
    int src = (r < nt) ? d_it[r] : d_ic[r - nt];
    const float4* in = (const float4*)(enc + ((size_t)src * S_STEPS + s) * DIM);
    float4 v = in[tid];

    __nv_bfloat162 h01 = {__float2bfloat16_rn(v.x), __float2bfloat16_rn(v.y)};
    __nv_bfloat162 h23 = {__float2bfloat16_rn(v.z), __float2bfloat16_rn(v.w)};
    size_t base = ((size_t)s * N_TOTAL + r) * DIM + (size_t)tid * 4;
    uint2 hv = { *(unsigned*)&h01, *(unsigned*)&h23 };
    *(uint2*)(d_Xhi + base) = hv;

    float nrm = v.x * v.x + v.y * v.y + v.z * v.z + v.w * v.w;
    for (int o = 16; o; o >>= 1) nrm += __shfl_down_sync(0xffffffffu, nrm, o);
    __shared__ float sn[2];
    if ((tid & 31) == 0) sn[tid >> 5] = nrm;
    __syncthreads();
    if (tid == 0) d_norm[s * N_TOTAL + r] = sn[0] + sn[1];
}

// ---------------- 3) mma.sync bf16 GEMM: CTA 128x128, warps 64x32 ------------
// grid (16,16,S), 256 threads (8 warps: 2 m x 4 n)
__global__ void __launch_bounds__(256, 2) gemm_kernel() {
    __shared__ __align__(16) unsigned char sm[21504];
    const int AHI = 0, BHI = 10240;
    float* rbuf = (float*)(sm + 20480);

    int tid = threadIdx.x, lane = tid & 31, wid = tid >> 5;
    int wm = wid >> 2, wn = wid & 3;
    int s = blockIdx.z;
    int nt = d_nt, nc = d_nc;
    int i0 = blockIdx.y * 128, j0 = blockIdx.x * 128;
    int pidx = s * 256 + blockIdx.y * 16 + blockIdx.x;

    if (i0 >= nt || j0 >= nc) {
        if (tid == 0) { d_pmax[pidx] = 0.0f; d_psum[pidx] = 0.0f; }
        return;
    }

    uint32_t sb = smem_u32(sm);
    size_t Xbase = (size_t)s * N_TOTAL * DIM;
    const uint4 z4 = make_uint4(0, 0, 0, 0);

    float c[4][4][4];
#pragma unroll
    for (int a = 0; a < 4; a++)
#pragma unroll
        for (int b = 0; b < 4; b++)
#pragma unroll
            for (int q = 0; q < 4; q++) c[a][b][q] = 0.0f;

    for (int chunk = 0; chunk < 8; chunk++) {
        int k0 = chunk * 32;
#pragma unroll
        for (int h = 0; h < 2; h++) {
            int idx = tid + h * 256;
            int row = idx >> 2, seg = idx & 3;
            uint32_t doff = (uint32_t)row * 80 + (uint32_t)seg * 16;
            size_t asrc = Xbase + (size_t)(i0 + row) * DIM + k0 + seg * 8;
            size_t bsrc = Xbase + (size_t)(nt + j0 + row) * DIM + k0 + seg * 8;
            uint4 av = (i0 + row < nt) ? *(const uint4*)(d_Xhi + asrc) : z4;
            uint4 bv = (j0 + row < nc) ? *(const uint4*)(d_Xhi + bsrc) : z4;
            *(uint4*)(sm + AHI + doff) = av;
            *(uint4*)(sm + BHI + doff) = bv;
        }
        __syncthreads();

#pragma unroll
        for (int ks = 0; ks < 32; ks += 16) {
            uint32_t colb = (uint32_t)(ks + ((lane >> 4) << 3)) * 2;
            uint32_t ah[4][4], bh2[2][4];
#pragma unroll
            for (int mt = 0; mt < 4; mt++) {
                uint32_t addr = sb + AHI + (uint32_t)(wm * 64 + mt * 16 + (lane & 15)) * 80 + colb;
                LDSM4(ah[mt], addr);
            }
#pragma unroll
            for (int pp = 0; pp < 2; pp++) {
                uint32_t addr = sb + BHI + (uint32_t)(wn * 32 + pp * 16 + (lane & 15)) * 80 + colb;
                LDSM4(bh2[pp], addr);
            }
#pragma unroll
            for (int mt = 0; mt < 4; mt++)
#pragma unroll
                for (int nn = 0; nn < 4; nn++) {
                    int pp = nn >> 1, od = nn & 1;
                    MMA_BF16(c[mt][nn], ah[mt], bh2[pp][od], bh2[pp][2 + od]);
                }
        }
        __syncthreads();
    }

    // stage nb norms in smem (reuse A region)
    float* nbs = (float*)(sm + AHI);
    for (int q = tid; q < 128; q += 256)
        nbs[q] = (j0 + q < nc) ? d_norm[s * N_TOTAL + nt + j0 + q] : 0.0f;
    __syncthreads();

    int rsU = (nc + 16) & ~15;
    float lmax = 0.0f, lsum = 0.0f;
#pragma unroll
    for (int mt = 0; mt < 4; mt++) {
        int gi0 = i0 + wm * 64 + mt * 16 + (lane >> 2);
        int gi1 = gi0 + 8;
        float na0 = (gi0 < nt) ? d_norm[s * N_TOTAL + gi0] : 0.0f;
        float na1 = (gi1 < nt) ? d_norm[s * N_TOTAL + gi1] : 0.0f;
#pragma unroll
        for (int nn = 0; nn < 4; nn++) {
            int lj = wn * 32 + nn * 8 + (lane & 3) * 2;
            int gj = j0 + lj;
            float nb0 = nbs[lj], nb1 = nbs[lj + 1];
            bool vj0 = gj < nc, vj1 = (gj + 1) < nc;
            float m00 = na0 + nb0 - 2.0f * c[mt][nn][0];
            float m01 = na0 + nb1 - 2.0f * c[mt][nn][1];
            float m10 = na1 + nb0 - 2.0f * c[mt][nn][2];
            float m11 = na1 + nb1 - 2.0f * c[mt][nn][3];
            if (gi0 < nt) {
                __half* Mr = d_Mh + (size_t)s * PER_TS + (size_t)gi0 * rsU + gj;
                if (vj0) { lmax = fmaxf(lmax, m00); lsum += m00; }
                if (vj1) { lmax = fmaxf(lmax, m01); lsum += m01; }
                if (vj0 && vj1) *(__half2*)Mr = __floats2half2_rn(m00, m01);
                else if (vj0)   *Mr = __float2half_rn(m00);
            }
            if (gi1 < nt) {
                __half* Mr = d_Mh + (size_t)s * PER_TS + (size_t)gi1 * rsU + gj;
                if (vj0) { lmax = fmaxf(lmax, m10); lsum += m10; }
                if (vj1) { lmax = fmaxf(lmax, m11); lsum += m11; }
                if (vj0 && vj1) *(__half2*)Mr = __floats2half2_rn(m10, m11);
                else if (vj0)   *Mr = __float2half_rn(m10);
            }
        }
    }

    rbuf[tid] = lmax; __syncthreads();
    for (int st = 128; st; st >>= 1) {
        if (tid < st) rbuf[tid] = fmaxf(rbuf[tid], rbuf[tid + st]);
        __syncthreads();
    }
    if (tid == 0) d_pmax[pidx] = rbuf[0];
    __syncthreads();
    rbuf[tid] = lsum; __syncthreads();
    for (int st = 128; st; st >>= 1) {
        if (tid < st) rbuf[tid] += rbuf[tid + st];
        __syncthreads();
    }
    if (tid == 0) d_psum[pidx] = rbuf[0];
}

// ---------------- 4) per-timestep stats --------------------------------------
__global__ void reduce_stats() {
    __shared__ float rb[256];
    int s = blockIdx.x, tid = threadIdx.x;
    float mv = d_pmax[s * 256 + tid];
    float sv = d_psum[s * 256 + tid];
    rb[tid] = mv; __syncthreads();
    for (int st = 128; st; st >>= 1) {
        if (tid < st) rb[tid] = fmaxf(rb[tid], rb[tid + st]);
        __syncthreads();
    }
    float mx = rb[0];
    __syncthreads();
    rb[tid] = sv; __syncthreads();
    for (int st = 128; st; st >>= 1) {
        if (tid < st) rb[tid] += rb[tid + st];
        __syncthreads();
    }
    if (tid == 0) {
        d_delta[s] = mx;
        d_lam[s] = ((float)d_nt * (float)d_nc) / rb[0];
    }
}

// ---------------- 5) persistent Sinkhorn: 32 clusters of 8 CTAs ---------------
__device__ __forceinline__ void colpass_f(
    const __half* Kb, const float* ub, float* zb, float (*red)[160],
    int ntp, int nc, int rsU, int Wc, int cbase, int lane, int wid, int tid,
    float bn, float bp)
{
    float acc[2][4] = {{0.f,0.f,0.f,0.f},{0.f,0.f,0.f,0.f}};
    int l4 = lane * 4;
    int jj0 = cbase + l4;
    int jj1 = jj0 + 128;
    bool v0 = (l4 < Wc) && (jj0 < rsU);
    bool v1 = (l4 + 128 < Wc) && (jj1 < rsU);
    for (int i = wid; i < ntp; i += 8) {
        float u = __ldcg(ub + i);
        const __half* Kr = Kb + (size_t)i * rsU;
        if (v0) {
            float4 f = h4_f4(*(const uint2*)(Kr + jj0));
            acc[0][0] = fmaf(f.x, u, acc[0][0]);
            acc[0][1] = fmaf(f.y, u, acc[0][1]);
            acc[0][2] = fmaf(f.z, u, acc[0][2]);
            acc[0][3] = fmaf(f.w, u, acc[0][3]);
        }
        if (v1) {
            float4 f = h4_f4(*(const uint2*)(Kr + jj1));
            acc[1][0] = fmaf(f.x, u, acc[1][0]);
            acc[1][1] = fmaf(f.y, u, acc[1][1]);
            acc[1][2] = fmaf(f.z, u, acc[1][2]);
            acc[1][3] = fmaf(f.w, u, acc[1][3]);
        }
    }
    if (v0) {
#pragma unroll
        for (int q = 0; q < 4; q++) red[wid][l4 + q] = acc[0][q];
    }
    if (v1) {
#pragma unroll
        for (int q = 0; q < 4; q++) red[wid][128 + l4 + q] = acc[1][q];
    }
    __syncthreads();
    for (int cc = tid; cc < Wc; cc += 256) {
        int j = cbase + cc;
        if (j >= rsU) continue;
        float t = red[0][cc];
#pragma unroll
        for (int w = 1; w < 8; w++) t += red[w][cc];
        float zv = (j < nc) ? (bn / t) : ((j == nc) ? (bp / t) : 0.0f);
        __stcg(zb + j, zv);
    }
    __syncthreads();
}

__device__ __forceinline__ void rowpass_f(
    const __half* Kb, float* ub, const float* zb,
    int r0, int r1, int nt, int rsU, int lane, int wid, float an, float ap)
{
    for (int i = r0 + wid; i < r1; i += 8) {
        const __half* Kr = Kb + (size_t)i * rsU;
        float acc = 0.0f;
        for (int jj = lane * 4; jj < rsU; jj += 128) {
            float4 kf = h4_f4(*(const uint2*)(Kr + jj));
            float4 zv = __ldcg((const float4*)(zb + jj));
            acc = fmaf(kf.x, zv.x, acc);
            acc = fmaf(kf.y, zv.y, acc);
            acc = fmaf(kf.z, zv.z, acc);
            acc = fmaf(kf.w, zv.w, acc);
        }
#pragma unroll
        for (int o = 16; o; o >>= 1) acc += __shfl_down_sync(0xffffffffu, acc, o);
        if (lane == 0) __stcg(ub + i, ((i < nt) ? an : ap) / acc);
    }
}

__global__ void __cluster_dims__(8, 1, 1) __launch_bounds__(256, 2) sink_cluster() {
    __shared__ float red[8][160];
    __shared__ float wsum[8];
    int bid = blockIdx.x;
    int s = bid >> 3, cr = bid & 7;
    int tid = threadIdx.x, lane = tid & 31, wid = tid >> 5;
    int nt = d_nt, nc = d_nc, ntp = nt + 1;
    int rsU = (nc + 16) & ~15;
    float lam = d_lam[s], delta = d_delta[s], p = d_p;
    float an = p / (float)nt, ap = 1.0f - p;
    float bn = (1.0f - p) / (float)nc, bp = p;
    __half* Mb = d_Mh + (size_t)s * PER_TS;
    __half* Kb = d_Kh + (size_t)s * PER_TS;
    float* ub = d_u + s * ZSTRIDE;
    float* zb = d_z + s * ZSTRIDE;

    // ---- Phase A: build K fp16 + M pads on row slice; init u slice ----
    int H = (ntp + 7) >> 3;
    int r0 = cr * H;
    int r1 = min(ntp, r0 + H);
    float kpad = fexpf_(-lam * delta) + 1e-6f;
    float kcorner = 1.0f + 1e-6f;
    for (int r = r0; r < r1; r++) {
        __half* Mw = Mb + (size_t)r * rsU;
        __half* Kr = Kb + (size_t)r * rsU;
        for (int c = tid * 2; c < rsU; c += 512) {
            float kk[2];
#pragma unroll
            for (int q = 0; q < 2; q++) {
                int cc = c + q;
                float kv;
                if (r < nt) {
                    if (cc < nc) {
                        kv = fexpf_(-lam * __half2float(Mw[cc])) + 1e-6f;
                    } else if (cc == nc) {
                        kv = kpad; Mw[cc] = __float2half_rn(delta);
                    } else {
                        kv = 0.0f; Mw[cc] = __float2half_rn(0.0f);
                    }
                } else {
                    if (cc < nc) { kv = kpad; Mw[cc] = __float2half_rn(delta); }
                    else if (cc == nc) { kv = kcorner; Mw[cc] = __float2half_rn(0.0f); }
                    else { kv = 0.0f; Mw[cc] = __float2half_rn(0.0f); }
                }
                kk[q] = kv;
            }
            __half2 h2 = __floats2half2_rn(kk[0], kk[1]);
            *(unsigned*)(Kr + c) = *(unsigned*)&h2;
        }
    }
    for (int i = r0 + tid; i < r1; i += 256) __stcg(ub + i, (i < nt) ? an : ap);
    CLUSTER_SYNC();

    // ---- Sinkhorn: 20 x (colpass, rowpass) + final colpass (v) ----
    int Wc = ((rsU >> 3) + 3) & ~3;
    int cbase = cr * Wc;
    for (int it = 0; it < 21; it++) {
        colpass_f(Kb, ub, zb, red, ntp, nc, rsU, Wc, cbase, lane, wid, tid, bn, bp);
        CLUSTER_SYNC();
        if (it == 20) break;
        rowpass_f(Kb, ub, zb, r0, r1, nt, rsU, lane, wid, an, ap);
        CLUSTER_SYNC();
    }

    // ---- finalsum on row slice: sum_i u_i * sum_j K_ij M_ij z_j ----
    float part = 0.0f;
    for (int i = r0 + wid; i < r1; i += 8) {
        const __half* Kr = Kb + (size_t)i * rsU;
        const __half* Mr = Mb + (size_t)i * rsU;
        float acc = 0.0f;
        for (int jj = lane * 4; jj < rsU; jj += 128) {
            float4 kf = h4_f4(*(const uint2*)(Kr + jj));
            float4 mf = h4_f4(*(const uint2*)(Mr + jj));
            float4 zv = __ldcg((const float4*)(zb + jj));
            acc = fmaf(kf.x * mf.x, zv.x, acc);
            acc = fmaf(kf.y * mf.y, zv.y, acc);
            acc = fmaf(kf.z * mf.z, zv.z, acc);
            acc = fmaf(kf.w * mf.w, zv.w, acc);
        }
#pragma unroll
        for (int o = 16; o; o >>= 1) acc += __shfl_down_sync(0xffffffffu, acc, o);
        if (lane == 0) part = fmaf(__ldcg(ub + i), acc, part);
    }
    if (lane == 0) wsum[wid] = part;
    __syncthreads();
    if (tid == 0) {
        float t = 0.0f;
#pragma unroll
        for (int w = 0; w < 8; w++) t += wsum[w];
        d_pfin[bid] = t;
    }
}

// ---------------- 6) final deterministic reduce ------------------------------
__global__ void finalreduce(float* __restrict__ out) {
    __shared__ float rb[256];
    int tid = threadIdx.x;
    rb[tid] = d_pfin[tid];
    __syncthreads();
    for (int st = 128; st; st >>= 1) {
        if (tid < st) rb[tid] += rb[tid + st];
        __syncthreads();
    }
    if (tid == 0) out[0] = 2.0f * rb[0];
}

// ---------------- launch -----------------------------------------------------
extern "C" void kernel_launch(void* const* d_in, const int* in_sizes, int n_in,
                              void* d_out, int out_size) {
    const float* enc = (const float*)d_in[0];
    const int*   t   = (const int*)d_in[2];
    float* out = (float*)d_out;

    part_kernel<<<1, 1024>>>(t);
    gather_kernel<<<dim3(N_TOTAL, S_STEPS), 64>>>(enc);
    gemm_kernel<<<dim3(16, 16, S_STEPS), 256>>>();
    reduce_stats<<<S_STEPS, 256>>>();
    sink_cluster<<<256, 256>>>();
    finalreduce<<<1, 256>>>(out);
}

// round 8
// speedup vs baseline: 2.8070x; 1.3156x over previous
#include <cuda_runtime.h>
#include <cuda_fp16.h>
#include <cuda_bf16.h>
#include <cstdint>

#define N_TOTAL 2048
#define S_STEPS 32
#define DIM 256
#define PER_TS 1507328      // >= rows_max(1205) * rsU_max(1216)
#define ZSTRIDE 2056

// ---------------- scratch (device globals; no dynamic allocation) ------------
__device__ __align__(16) __half d_Mh[(size_t)S_STEPS * PER_TS];
__device__ __align__(16) __half d_Kh[(size_t)S_STEPS * PER_TS];
__device__ __align__(16) __nv_bfloat16 d_Xhi[(size_t)S_STEPS * N_TOTAL * DIM];
__device__ float d_norm[S_STEPS * N_TOTAL];
__device__ int   d_it[N_TOTAL], d_ic[N_TOTAL];
__device__ int   d_nt, d_nc;
__device__ float d_p;
__device__ float d_lam[S_STEPS], d_delta[S_STEPS];
__device__ __align__(16) float d_u[S_STEPS * ZSTRIDE];
__device__ __align__(16) float d_z[S_STEPS * ZSTRIDE];
__device__ float d_pmax[S_STEPS * 256];
__device__ float d_psum[S_STEPS * 256];
__device__ float d_pfin[256];

// ---------------- fast exp (Cephes, FMA pipe; args in [-8, 0]) ---------------
__device__ __forceinline__ float fexpf_(float x) {
    float z = fmaf(x, 1.4426950408889634f, 12582912.0f);
    float n = z - 12582912.0f;
    float r = fmaf(n, -0.693359375f, x);
    r = fmaf(n, 2.12194440e-4f, r);
    float p = 1.9875691500e-4f;
    p = fmaf(p, r, 1.3981999507e-3f);
    p = fmaf(p, r, 8.3334519073e-3f);
    p = fmaf(p, r, 4.1665795894e-2f);
    p = fmaf(p, r, 1.6666665459e-1f);
    p = fmaf(p, r, 5.0000001201e-1f);
    float e = fmaf(r * r, p, r) + 1.0f;
    int ni = (int)n;
    return __int_as_float(__float_as_int(e) + (ni << 23));
}

__device__ __forceinline__ uint32_t smem_u32(const void* p) {
    uint32_t a;
    asm("{ .reg .u64 t; cvta.to.shared.u64 t, %1; cvt.u32.u64 %0, t; }" : "=r"(a) : "l"(p));
    return a;
}

// 4 halves -> float4
__device__ __forceinline__ float4 h4_f4(uint2 w) {
    float2 a = __half22float2(*reinterpret_cast<__half2*>(&w.x));
    float2 b = __half22float2(*reinterpret_cast<__half2*>(&w.y));
    return make_float4(a.x, a.y, b.x, b.y);
}

#define CLUSTER_SYNC() do { \
    asm volatile("barrier.cluster.arrive.aligned;" ::: "memory"); \
    asm volatile("barrier.cluster.wait.aligned;" ::: "memory"); } while (0)

#define LDSM4(R, addr) \
    asm volatile("ldmatrix.sync.aligned.m8n8.x4.shared.b16 {%0,%1,%2,%3}, [%4];" \
        : "=r"((R)[0]), "=r"((R)[1]), "=r"((R)[2]), "=r"((R)[3]) : "r"(addr))

#define MMA_BF16(C, A, b0_, b1_) \
    asm volatile("mma.sync.aligned.m16n8k16.row.col.f32.bf16.bf16.f32 " \
        "{%0,%1,%2,%3}, {%4,%5,%6,%7}, {%8,%9}, {%0,%1,%2,%3};" \
        : "+f"((C)[0]), "+f"((C)[1]), "+f"((C)[2]), "+f"((C)[3]) \
        : "r"((A)[0]), "r"((A)[1]), "r"((A)[2]), "r"((A)[3]), "r"(b0_), "r"(b1_))

#define CP_ASYNC16(smaddr, gptr, srcsz) \
    asm volatile("cp.async.cg.shared.global [%0], [%1], 16, %2;" \
        :: "r"(smaddr), "l"(gptr), "r"(srcsz))

// ---------------- 1) partition indices (deterministic, single block) ---------
__global__ void part_kernel(const int* __restrict__ t) {
    __shared__ int wcntT[64];
    __shared__ int wprefT[64], wprefC[64];
    int tid = threadIdx.x, lane = tid & 31, wid = tid >> 5;
    for (int c = wid; c < 64; c += 32) {
        int e = c * 32 + lane;
        int f = t[e] > 0;
        unsigned m = __ballot_sync(0xffffffffu, f);
        if (lane == 0) wcntT[c] = __popc(m);
    }
    __syncthreads();
    if (tid == 0) {
        int aT = 0;
        for (int c = 0; c < 64; c++) {
            wprefT[c] = aT;
            wprefC[c] = c * 32 - aT;
            aT += wcntT[c];
        }
        d_nt = aT;
        d_nc = N_TOTAL - aT;
        d_p  = (float)aT / (float)N_TOTAL;
    }
    __syncthreads();
    for (int c = wid; c < 64; c += 32) {
        int e = c * 32 + lane;
        int f = t[e] > 0;
        unsigned m  = __ballot_sync(0xffffffffu, f);
        unsigned lt = ((1u << lane) - 1u);
        if (f) d_it[wprefT[c] + __popc(m & lt)]  = e;
        else   d_ic[wprefC[c] + __popc(~m & lt)] = e;
    }
}

// ---------------- 2) gather rows -> bf16 + fp32 row norms --------------------
// grid (N_TOTAL, S), 64 threads
__global__ void gather_kernel(const float* __restrict__ enc) {
    int r = blockIdx.x, s = blockIdx.y, tid = threadIdx.x;
    int nt = d_nt;
    int src = (r < nt) ? d_it[r] : d_ic[r - nt];
    const float4* in = (const float4*)(enc + ((size_t)src * S_STEPS + s) * DIM);
    float4 v = in[tid];

    __nv_bfloat162 h01 = {__float2bfloat16_rn(v.x), __float2bfloat16_rn(v.y)};
    __nv_bfloat162 h23 = {__float2bfloat16_rn(v.z), __float2bfloat16_rn(v.w)};
    size_t base = ((size_t)s * N_TOTAL + r) * DIM + (size_t)tid * 4;
    uint2 hv = { *(unsigned*)&h01, *(unsigned*)&h23 };
    *(uint2*)(d_Xhi + base) = hv;

    float nrm = v.x * v.x + v.y * v.y + v.z * v.z + v.w * v.w;
    for (int o = 16; o; o >>= 1) nrm += __shfl_down_sync(0xffffffffu, nrm, o);
    __shared__ float sn[2];
    if ((tid & 31) == 0) sn[tid >> 5] = nrm;
    __syncthreads();
    if (tid == 0) d_norm[s * N_TOTAL + r] = sn[0] + sn[1];
}

// ---------------- 3) bf16 GEMM w/ cp.async double buffer ---------------------
// grid (16,16,S), 256 threads (8 warps: 2 m x 4 n), CTA tile 128x128
__global__ void __launch_bounds__(256, 2) gemm_kernel() {
    __shared__ __align__(16) unsigned char sm[41984];
    // buf b: A at b*20480, B at b*20480+10240; rbuf at 40960
    float* rbuf = (float*)(sm + 40960);

    int tid = threadIdx.x, lane = tid & 31, wid = tid >> 5;
    int wm = wid >> 2, wn = wid & 3;
    int s = blockIdx.z;
    int nt = d_nt, nc = d_nc;
    int i0 = blockIdx.y * 128, j0 = blockIdx.x * 128;
    int pidx = s * 256 + blockIdx.y * 16 + blockIdx.x;

    if (i0 >= nt || j0 >= nc) {
        if (tid == 0) { d_pmax[pidx] = 0.0f; d_psum[pidx] = 0.0f; }
        return;
    }

    uint32_t sb = smem_u32(sm);
    size_t Xbase = (size_t)s * N_TOTAL * DIM;

    // per-thread load geometry (2 rows per thread via h loop)
    int rowA[2], segA[2];
    bool va[2], vb[2];
    const __nv_bfloat16 *gA[2], *gB[2];
#pragma unroll
    for (int h = 0; h < 2; h++) {
        int idx = tid + h * 256;
        rowA[h] = idx >> 2; segA[h] = idx & 3;
        va[h] = (i0 + rowA[h]) < nt;
        vb[h] = (j0 + rowA[h]) < nc;
        int ra = va[h] ? (i0 + rowA[h]) : 0;
        int rb = vb[h] ? (j0 + rowA[h]) : 0;
        gA[h] = d_Xhi + Xbase + (size_t)ra * DIM + segA[h] * 8;
        gB[h] = d_Xhi + Xbase + (size_t)(nt + rb) * DIM + segA[h] * 8;
    }

    float c[4][4][4];
#pragma unroll
    for (int a = 0; a < 4; a++)
#pragma unroll
        for (int b = 0; b < 4; b++)
#pragma unroll
            for (int q = 0; q < 4; q++) c[a][b][q] = 0.0f;

    // issue chunk loads into buffer (chunk&1)
    auto issue = [&](int chunk) {
        int k0 = chunk * 32;
        uint32_t bufo = (uint32_t)(chunk & 1) * 20480u;
#pragma unroll
        for (int h = 0; h < 2; h++) {
            uint32_t doff = (uint32_t)rowA[h] * 80 + (uint32_t)segA[h] * 16;
            CP_ASYNC16(sb + bufo + doff, gA[h] + k0, va[h] ? 16 : 0);
            CP_ASYNC16(sb + bufo + 10240 + doff, gB[h] + k0, vb[h] ? 16 : 0);
        }
        asm volatile("cp.async.commit_group;");
    };

    issue(0);

    for (int chunk = 0; chunk < 8; chunk++) {
        if (chunk < 7) {
            issue(chunk + 1);
            asm volatile("cp.async.wait_group 1;");
        } else {
            asm volatile("cp.async.wait_group 0;");
        }
        __syncthreads();

        uint32_t bufo = (uint32_t)(chunk & 1) * 20480u;
#pragma unroll
        for (int ks = 0; ks < 32; ks += 16) {
            uint32_t colb = (uint32_t)(ks + ((lane >> 4) << 3)) * 2;
            uint32_t ah[4][4], bh2[2][4];
#pragma unroll
            for (int mt = 0; mt < 4; mt++) {
                uint32_t addr = sb + bufo + (uint32_t)(wm * 64 + mt * 16 + (lane & 15)) * 80 + colb;
                LDSM4(ah[mt], addr);
            }
#pragma unroll
            for (int pp = 0; pp < 2; pp++) {
                uint32_t addr = sb + bufo + 10240 + (uint32_t)(wn * 32 + pp * 16 + (lane & 15)) * 80 + colb;
                LDSM4(bh2[pp], addr);
            }
#pragma unroll
            for (int mt = 0; mt < 4; mt++)
#pragma unroll
                for (int nn = 0; nn < 4; nn++) {
                    int pp = nn >> 1, od = nn & 1;
                    MMA_BF16(c[mt][nn], ah[mt], bh2[pp][od], bh2[pp][2 + od]);
                }
        }
        __syncthreads();
    }

    // stage nb norms in smem
    float* nbs = (float*)sm;
    for (int q = tid; q < 128; q += 256)
        nbs[q] = (j0 + q < nc) ? d_norm[s * N_TOTAL + nt + j0 + q] : 0.0f;
    __syncthreads();

    int rsU = (nc + 16) & ~15;
    float lmax = 0.0f, lsum = 0.0f;
#pragma unroll
    for (int mt = 0; mt < 4; mt++) {
        int gi0 = i0 + wm * 64 + mt * 16 + (lane >> 2);
        int gi1 = gi0 + 8;
        float na0 = (gi0 < nt) ? d_norm[s * N_TOTAL + gi0] : 0.0f;
        float na1 = (gi1 < nt) ? d_norm[s * N_TOTAL + gi1] : 0.0f;
#pragma unroll
        for (int nn = 0; nn < 4; nn++) {
            int lj = wn * 32 + nn * 8 + (lane & 3) * 2;
            int gj = j0 + lj;
            float nb0 = nbs[lj], nb1 = nbs[lj + 1];
            bool vj0 = gj < nc, vj1 = (gj + 1) < nc;
            float m00 = na0 + nb0 - 2.0f * c[mt][nn][0];
            float m01 = na0 + nb1 - 2.0f * c[mt][nn][1];
            float m10 = na1 + nb0 - 2.0f * c[mt][nn][2];
            float m11 = na1 + nb1 - 2.0f * c[mt][nn][3];
            if (gi0 < nt) {
                __half* Mr = d_Mh + (size_t)s * PER_TS + (size_t)gi0 * rsU + gj;
                if (vj0) { lmax = fmaxf(lmax, m00); lsum += m00; }
                if (vj1) { lmax = fmaxf(lmax, m01); lsum += m01; }
                if (vj0 && vj1) *(__half2*)Mr = __floats2half2_rn(m00, m01);
                else if (vj0)   *Mr = __float2half_rn(m00);
            }
            if (gi1 < nt) {
                __half* Mr = d_Mh + (size_t)s * PER_TS + (size_t)gi1 * rsU + gj;
                if (vj0) { lmax = fmaxf(lmax, m10); lsum += m10; }
                if (vj1) { lmax = fmaxf(lmax, m11); lsum += m11; }
                if (vj0 && vj1) *(__half2*)Mr = __floats2half2_rn(m10, m11);
                else if (vj0)   *Mr = __float2half_rn(m10);
            }
        }
    }

    rbuf[tid] = lmax; __syncthreads();
    for (int st = 128; st; st >>= 1) {
        if (tid < st) rbuf[tid] = fmaxf(rbuf[tid], rbuf[tid + st]);
        __syncthreads();
    }
    if (tid == 0) d_pmax[pidx] = rbuf[0];
    __syncthreads();
    rbuf[tid] = lsum; __syncthreads();
    for (int st = 128; st; st >>= 1) {
        if (tid < st) rbuf[tid] += rbuf[tid + st];
        __syncthreads();
    }
    if (tid == 0) d_psum[pidx] = rbuf[0];
}

// ---------------- 4) per-timestep stats --------------------------------------
__global__ void reduce_stats() {
    __shared__ float rb[256];
    int s = blockIdx.x, tid = threadIdx.x;
    float mv = d_pmax[s * 256 + tid];
    float sv = d_psum[s * 256 + tid];
    rb[tid] = mv; __syncthreads();
    for (int st = 128; st; st >>= 1) {
        if (tid < st) rb[tid] = fmaxf(rb[tid], rb[tid + st]);
        __syncthreads();
    }
    float mx = rb[0];
    __syncthreads();
    rb[tid] = sv; __syncthreads();
    for (int st = 128; st; st >>= 1) {
        if (tid < st) rb[tid] += rb[tid + st];
        __syncthreads();
    }
    if (tid == 0) {
        d_delta[s] = mx;
        d_lam[s] = ((float)d_nt * (float)d_nc) / rb[0];
    }
}

// ---------------- 5) persistent Sinkhorn: 32 clusters of 8 CTAs, 512 thr -----
__device__ __forceinline__ void colpass_f(
    const __half* Kb, const float* ub, float* zb, float (*red)[164],
    int ntp, int nc, int rsU, int Wc, int cbase, int lane, int wid, int tid,
    float bn, float bp)
{
    float acc[2][4] = {{0.f,0.f,0.f,0.f},{0.f,0.f,0.f,0.f}};
    int l4 = lane * 4;
    int jj0 = cbase + l4;
    int jj1 = jj0 + 128;
    bool v0 = (l4 < Wc) && (jj0 < rsU);
    bool v1 = (l4 + 128 < Wc) && (jj1 < rsU);
#pragma unroll 4
    for (int i = wid; i < ntp; i += 16) {
        float u = __ldcg(ub + i);
        const __half* Kr = Kb + (size_t)i * rsU;
        if (v0) {
            float4 f = h4_f4(*(const uint2*)(Kr + jj0));
            acc[0][0] = fmaf(f.x, u, acc[0][0]);
            acc[0][1] = fmaf(f.y, u, acc[0][1]);
            acc[0][2] = fmaf(f.z, u, acc[0][2]);
            acc[0][3] = fmaf(f.w, u, acc[0][3]);
        }
        if (v1) {
            float4 f = h4_f4(*(const uint2*)(Kr + jj1));
            acc[1][0] = fmaf(f.x, u, acc[1][0]);
            acc[1][1] = fmaf(f.y, u, acc[1][1]);
            acc[1][2] = fmaf(f.z, u, acc[1][2]);
            acc[1][3] = fmaf(f.w, u, acc[1][3]);
        }
    }
    if (v0) {
#pragma unroll
        for (int q = 0; q < 4; q++) red[wid][l4 + q] = acc[0][q];
    }
    if (v1) {
#pragma unroll
        for (int q = 0; q < 4; q++) red[wid][128 + l4 + q] = acc[1][q];
    }
    __syncthreads();
    for (int cc = tid; cc < Wc; cc += 512) {
        int j = cbase + cc;
        if (j >= rsU) continue;
        float t = red[0][cc];
#pragma unroll
        for (int w = 1; w < 16; w++) t += red[w][cc];
        float zv = (j < nc) ? (bn / t) : ((j == nc) ? (bp / t) : 0.0f);
        __stcg(zb + j, zv);
    }
    __syncthreads();
}

__device__ __forceinline__ void rowpass_f(
    const __half* Kb, float* ub, const float* zb,
    int r0, int r1, int nt, int rsU, int lane, int wid, float an, float ap)
{
    for (int i = r0 + wid; i < r1; i += 32) {
        int i2 = i + 16;
        bool has2 = i2 < r1;
        const __half* Kr1 = Kb + (size_t)i * rsU;
        const __half* Kr2 = Kb + (size_t)(has2 ? i2 : i) * rsU;
        float a1 = 0.0f, a2 = 0.0f;
#pragma unroll 2
        for (int jj = lane * 4; jj < rsU; jj += 128) {
            float4 zv = __ldcg((const float4*)(zb + jj));
            float4 k1 = h4_f4(*(const uint2*)(Kr1 + jj));
            float4 k2 = h4_f4(*(const uint2*)(Kr2 + jj));
            a1 = fmaf(k1.x, zv.x, a1); a1 = fmaf(k1.y, zv.y, a1);
            a1 = fmaf(k1.z, zv.z, a1); a1 = fmaf(k1.w, zv.w, a1);
            a2 = fmaf(k2.x, zv.x, a2); a2 = fmaf(k2.y, zv.y, a2);
            a2 = fmaf(k2.z, zv.z, a2); a2 = fmaf(k2.w, zv.w, a2);
        }
#pragma unroll
        for (int o = 16; o; o >>= 1) {
            a1 += __shfl_down_sync(0xffffffffu, a1, o);
            a2 += __shfl_down_sync(0xffffffffu, a2, o);
        }
        if (lane == 0) {
            __stcg(ub + i, ((i < nt) ? an : ap) / a1);
            if (has2) __stcg(ub + i2, ((i2 < nt) ? an : ap) / a2);
        }
    }
}

__global__ void __cluster_dims__(8, 1, 1) __launch_bounds__(512, 2) sink_cluster() {
    __shared__ float red[16][164];
    __shared__ float wsum[16];
    int bid = blockIdx.x;
    int s = bid >> 3, cr = bid & 7;
    int tid = threadIdx.x, lane = tid & 31, wid = tid >> 5;
    int nt = d_nt, nc = d_nc, ntp = nt + 1;
    int rsU = (nc + 16) & ~15;
    float lam = d_lam[s], delta = d_delta[s], p = d_p;
    float an = p / (float)nt, ap = 1.0f - p;
    float bn = (1.0f - p) / (float)nc, bp = p;
    __half* Mb = d_Mh + (size_t)s * PER_TS;
    __half* Kb = d_Kh + (size_t)s * PER_TS;
    float* ub = d_u + s * ZSTRIDE;
    float* zb = d_z + s * ZSTRIDE;

    // ---- Phase A: build K fp16 + M pads on row slice; init u slice ----
    int H = (ntp + 7) >> 3;
    int r0 = cr * H;
    int r1 = min(ntp, r0 + H);
    float kpad = fexpf_(-lam * delta) + 1e-6f;
    float kcorner = 1.0f + 1e-6f;
    for (int r = r0; r < r1; r++) {
        __half* Mw = Mb + (size_t)r * rsU;
        __half* Kr = Kb + (size_t)r * rsU;
        for (int c = tid * 2; c < rsU; c += 1024) {
            float kk[2];
#pragma unroll
            for (int q = 0; q < 2; q++) {
                int cc = c + q;
                float kv;
                if (r < nt) {
                    if (cc < nc) {
                        kv = fexpf_(-lam * __half2float(Mw[cc])) + 1e-6f;
                    } else if (cc == nc) {
                        kv = kpad; Mw[cc] = __float2half_rn(delta);
                    } else {
                        kv = 0.0f; Mw[cc] = __float2half_rn(0.0f);
                    }
                } else {
                    if (cc < nc) { kv = kpad; Mw[cc] = __float2half_rn(delta); }
                    else if (cc == nc) { kv = kcorner; Mw[cc] = __float2half_rn(0.0f); }
                    else { kv = 0.0f; Mw[cc] = __float2half_rn(0.0f); }
                }
                kk[q] = kv;
            }
            __half2 h2 = __floats2half2_rn(kk[0], kk[1]);
            *(unsigned*)(Kr + c) = *(unsigned*)&h2;
        }
    }
    for (int i = r0 + tid; i < r1; i += 512) __stcg(ub + i, (i < nt) ? an : ap);
    CLUSTER_SYNC();

    // ---- Sinkhorn: 20 x (colpass, rowpass) + final colpass (v) ----
    int Wc = ((rsU >> 3) + 3) & ~3;
    int cbase = cr * Wc;
    for (int it = 0; it < 21; it++) {
        colpass_f(Kb, ub, zb, red, ntp, nc, rsU, Wc, cbase, lane, wid, tid, bn, bp);
        CLUSTER_SYNC();
        if (it == 20) break;
        rowpass_f(Kb, ub, zb, r0, r1, nt, rsU, lane, wid, an, ap);
        CLUSTER_SYNC();
    }

    // ---- finalsum on row slice: sum_i u_i * sum_j K_ij M_ij z_j ----
    float part = 0.0f;
    for (int i = r0 + wid; i < r1; i += 32) {
        int i2 = i + 16;
        bool has2 = i2 < r1;
        const __half* Kr1 = Kb + (size_t)i * rsU;
        const __half* Mr1 = Mb + (size_t)i * rsU;
        const __half* Kr2 = Kb + (size_t)(has2 ? i2 : i) * rsU;
        const __half* Mr2 = Mb + (size_t)(has2 ? i2 : i) * rsU;
        float a1 = 0.0f, a2 = 0.0f;
        for (int jj = lane * 4; jj < rsU; jj += 128) {
            float4 zv = __ldcg((const float4*)(zb + jj));
            float4 k1 = h4_f4(*(const uint2*)(Kr1 + jj));
            float4 m1 = h4_f4(*(const uint2*)(Mr1 + jj));
            float4 k2 = h4_f4(*(const uint2*)(Kr2 + jj));
            float4 m2 = h4_f4(*(const uint2*)(Mr2 + jj));
            a1 = fmaf(k1.x * m1.x, zv.x, a1); a1 = fmaf(k1.y * m1.y, zv.y, a1);
            a1 = fmaf(k1.z * m1.z, zv.z, a1); a1 = fmaf(k1.w * m1.w, zv.w, a1);
            a2 = fmaf(k2.x * m2.x, zv.x, a2); a2 = fmaf(k2.y * m2.y, zv.y, a2);
            a2 = fmaf(k2.z * m2.z, zv.z, a2); a2 = fmaf(k2.w * m2.w, zv.w, a2);
        }
#pragma unroll
        for (int o = 16; o; o >>= 1) {
            a1 += __shfl_down_sync(0xffffffffu, a1, o);
            a2 += __shfl_down_sync(0xffffffffu, a2, o);
        }
        if (lane == 0) {
            part = fmaf(__ldcg(ub + i), a1, part);
            if (has2) part = fmaf(__ldcg(ub + i2), a2, part);
        }
    }
    if (lane == 0) wsum[wid] = part;
    __syncthreads();
    if (tid == 0) {
        float t = 0.0f;
#pragma unroll
        for (int w = 0; w < 16; w++) t += wsum[w];
        d_pfin[bid] = t;
    }
}

// ---------------- 6) final deterministic reduce ------------------------------
__global__ void finalreduce(float* __restrict__ out) {
    __shared__ float rb[256];
    int tid = threadIdx.x;
    rb[tid] = d_pfin[tid];
    __syncthreads();
    for (int st = 128; st; st >>= 1) {
        if (tid < st) rb[tid] += rb[tid + st];
        __syncthreads();
    }
    if (tid == 0) out[0] = 2.0f * rb[0];
}

// ---------------- launch -----------------------------------------------------
extern "C" void kernel_launch(void* const* d_in, const int* in_sizes, int n_in,
                              void* d_out, int out_size) {
    const float* enc = (const float*)d_in[0];
    const int*   t   = (const int*)d_in[2];
    float* out = (float*)d_out;

    part_kernel<<<1, 1024>>>(t);
    gather_kernel<<<dim3(N_TOTAL, S_STEPS), 64>>>(enc);
    gemm_kernel<<<dim3(16, 16, S_STEPS), 256>>>();
    reduce_stats<<<S_STEPS, 256>>>();
    sink_cluster<<<256, 512>>>();
    finalreduce<<<1, 256>>>(out);
}

// round 9
// speedup vs baseline: 2.9464x; 1.0496x over previous
#include <cuda_runtime.h>
#include <cuda_fp16.h>
#include <cuda_bf16.h>
#include <cstdint>

#define N_TOTAL 2048
#define S_STEPS 32
#define DIM 256
#define PER_TS 1507328      // >= rows_max * rsU_max for realistic splits
#define ZSTRIDE 2056

// ---------------- scratch (device globals; no dynamic allocation) ------------
__device__ __align__(16) __half d_Mh[(size_t)S_STEPS * PER_TS];
__device__ __align__(16) __half d_Kh[(size_t)S_STEPS * PER_TS];
__device__ __align__(16) __nv_bfloat16 d_Xhi[(size_t)S_STEPS * N_TOTAL * DIM];
__device__ float d_norm[S_STEPS * N_TOTAL];
__device__ int   d_it[N_TOTAL], d_ic[N_TOTAL];
__device__ int   d_nt, d_nc;
__device__ float d_p;
__device__ float d_lam[S_STEPS], d_delta[S_STEPS];
__device__ __align__(16) float d_u[S_STEPS * ZSTRIDE];
__device__ __align__(16) float d_z[S_STEPS * ZSTRIDE];
__device__ float d_pmax[S_STEPS * 256];
__device__ float d_psum[S_STEPS * 256];
__device__ float d_pfin[256];

// ---------------- fast exp (Cephes, FMA pipe; args in [-8, 0]) ---------------
__device__ __forceinline__ float fexpf_(float x) {
    float z = fmaf(x, 1.4426950408889634f, 12582912.0f);
    float n = z - 12582912.0f;
    float r = fmaf(n, -0.693359375f, x);
    r = fmaf(n, 2.12194440e-4f, r);
    float p = 1.9875691500e-4f;
    p = fmaf(p, r, 1.3981999507e-3f);
    p = fmaf(p, r, 8.3334519073e-3f);
    p = fmaf(p, r, 4.1665795894e-2f);
    p = fmaf(p, r, 1.6666665459e-1f);
    p = fmaf(p, r, 5.0000001201e-1f);
    float e = fmaf(r * r, p, r) + 1.0f;
    int ni = (int)n;
    return __int_as_float(__float_as_int(e) + (ni << 23));
}

__device__ __forceinline__ uint32_t smem_u32(const void* p) {
    uint32_t a;
    asm("{ .reg .u64 t; cvta.to.shared.u64 t, %1; cvt.u32.u64 %0, t; }" : "=r"(a) : "l"(p));
    return a;
}

// 4 halves -> float4
__device__ __forceinline__ float4 h4_f4(uint2 w) {
    float2 a = __half22float2(*reinterpret_cast<__half2*>(&w.x));
    float2 b = __half22float2(*reinterpret_cast<__half2*>(&w.y));
    return make_float4(a.x, a.y, b.x, b.y);
}

#define CLUSTER_SYNC() do { \
    asm volatile("barrier.cluster.arrive.aligned;" ::: "memory"); \
    asm volatile("barrier.cluster.wait.aligned;" ::: "memory"); } while (0)

#define LDSM4(R, addr) \
    asm volatile("ldmatrix.sync.aligned.m8n8.x4.shared.b16 {%0,%1,%2,%3}, [%4];" \
        : "=r"((R)[0]), "=r"((R)[1]), "=r"((R)[2]), "=r"((R)[3]) : "r"(addr))

#define MMA_BF16(C, A, b0_, b1_) \
    asm volatile("mma.sync.aligned.m16n8k16.row.col.f32.bf16.bf16.f32 " \
        "{%0,%1,%2,%3}, {%4,%5,%6,%7}, {%8,%9}, {%0,%1,%2,%3};" \
        : "+f"((C)[0]), "+f"((C)[1]), "+f"((C)[2]), "+f"((C)[3]) \
        : "r"((A)[0]), "r"((A)[1]), "r"((A)[2]), "r"((A)[3]), "r"(b0_), "r"(b1_))

#define CP_ASYNC16(smaddr, gptr, srcsz) \
    asm volatile("cp.async.cg.shared.global [%0], [%1], 16, %2;" \
        :: "r"(smaddr), "l"(gptr), "r"(srcsz))

// ---------------- 1) partition indices (deterministic, single block) ---------
__global__ void part_kernel(const int* __restrict__ t) {
    __shared__ int wcntT[64];
    __shared__ int wprefT[64], wprefC[64];
    int tid = threadIdx.x, lane = tid & 31, wid = tid >> 5;
    for (int c = wid; c < 64; c += 32) {
        int e = c * 32 + lane;
        int f = t[e] > 0;
        unsigned m = __ballot_sync(0xffffffffu, f);
        if (lane == 0) wcntT[c] = __popc(m);
    }
    __syncthreads();
    if (tid == 0) {
        int aT = 0;
        for (int c = 0; c < 64; c++) {
            wprefT[c] = aT;
            wprefC[c] = c * 32 - aT;
            aT += wcntT[c];
        }
        d_nt = aT;
        d_nc = N_TOTAL - aT;
        d_p  = (float)aT / (float)N_TOTAL;
    }
    __syncthreads();
    for (int c = wid; c < 64; c += 32) {
        int e = c * 32 + lane;
        int f = t[e] > 0;
        unsigned m  = __ballot_sync(0xffffffffu, f);
        unsigned lt = ((1u << lane) - 1u);
        if (f) d_it[wprefT[c] + __popc(m & lt)]  = e;
        else   d_ic[wprefC[c] + __popc(~m & lt)] = e;
    }
}

// ---------------- 2) gather rows -> bf16 + fp32 row norms --------------------
// grid (N_TOTAL, S), 64 threads
__global__ void gather_kernel(const float* __restrict__ enc) {
    int r = blockIdx.x, s = blockIdx.y, tid = threadIdx.x;
    int nt = d_nt;
    int src = (r < nt) ? d_it[r] : d_ic[r - nt];
    const float4* in = (const float4*)(enc + ((size_t)src * S_STEPS + s) * DIM);
    float4 v = in[tid];

    __nv_bfloat162 h01 = {__float2bfloat16_rn(v.x), __float2bfloat16_rn(v.y)};
    __nv_bfloat162 h23 = {__float2bfloat16_rn(v.z), __float2bfloat16_rn(v.w)};
    size_t base = ((size_t)s * N_TOTAL + r) * DIM + (size_t)tid * 4;
    uint2 hv = { *(unsigned*)&h01, *(unsigned*)&h23 };
    *(uint2*)(d_Xhi + base) = hv;

    float nrm = v.x * v.x + v.y * v.y + v.z * v.z + v.w * v.w;
    for (int o = 16; o; o >>= 1) nrm += __shfl_down_sync(0xffffffffu, nrm, o);
    __shared__ float sn[2];
    if ((tid & 31) == 0) sn[tid >> 5] = nrm;
    __syncthreads();
    if (tid == 0) d_norm[s * N_TOTAL + r] = sn[0] + sn[1];
}

// ---------------- 3) bf16 GEMM w/ cp.async double buffer ---------------------
// grid (16,16,S), 256 threads (8 warps: 2 m x 4 n), CTA tile 128x128
__global__ void __launch_bounds__(256, 2) gemm_kernel() {
    __shared__ __align__(16) unsigned char sm[41984];
    float* rbuf = (float*)(sm + 40960);

    int tid = threadIdx.x, lane = tid & 31, wid = tid >> 5;
    int wm = wid >> 2, wn = wid & 3;
    int s = blockIdx.z;
    int nt = d_nt, nc = d_nc;
    int i0 = blockIdx.y * 128, j0 = blockIdx.x * 128;
    int pidx = s * 256 + blockIdx.y * 16 + blockIdx.x;

    if (i0 >= nt || j0 >= nc) {
        if (tid == 0) { d_pmax[pidx] = 0.0f; d_psum[pidx] = 0.0f; }
        return;
    }

    uint32_t sb = smem_u32(sm);
    size_t Xbase = (size_t)s * N_TOTAL * DIM;

    int rowA[2], segA[2];
    bool va[2], vb[2];
    const __nv_bfloat16 *gA[2], *gB[2];
#pragma unroll
    for (int h = 0; h < 2; h++) {
        int idx = tid + h * 256;
        rowA[h] = idx >> 2; segA[h] = idx & 3;
        va[h] = (i0 + rowA[h]) < nt;
        vb[h] = (j0 + rowA[h]) < nc;
        int ra = va[h] ? (i0 + rowA[h]) : 0;
        int rb = vb[h] ? (j0 + rowA[h]) : 0;
        gA[h] = d_Xhi + Xbase + (size_t)ra * DIM + segA[h] * 8;
        gB[h] = d_Xhi + Xbase + (size_t)(nt + rb) * DIM + segA[h] * 8;
    }

    float c[4][4][4];
#pragma unroll
    for (int a = 0; a < 4; a++)
#pragma unroll
        for (int b = 0; b < 4; b++)
#pragma unroll
            for (int q = 0; q < 4; q++) c[a][b][q] = 0.0f;

    auto issue = [&](int chunk) {
        int k0 = chunk * 32;
        uint32_t bufo = (uint32_t)(chunk & 1) * 20480u;
#pragma unroll
        for (int h = 0; h < 2; h++) {
            uint32_t doff = (uint32_t)rowA[h] * 80 + (uint32_t)segA[h] * 16;
            CP_ASYNC16(sb + bufo + doff, gA[h] + k0, va[h] ? 16 : 0);
            CP_ASYNC16(sb + bufo + 10240 + doff, gB[h] + k0, vb[h] ? 16 : 0);
        }
        asm volatile("cp.async.commit_group;");
    };

    issue(0);

    for (int chunk = 0; chunk < 8; chunk++) {
        if (chunk < 7) {
            issue(chunk + 1);
            asm volatile("cp.async.wait_group 1;");
        } else {
            asm volatile("cp.async.wait_group 0;");
        }
        __syncthreads();

        uint32_t bufo = (uint32_t)(chunk & 1) * 20480u;
#pragma unroll
        for (int ks = 0; ks < 32; ks += 16) {
            uint32_t colb = (uint32_t)(ks + ((lane >> 4) << 3)) * 2;
            uint32_t ah[4][4], bh2[2][4];
#pragma unroll
            for (int mt = 0; mt < 4; mt++) {
                uint32_t addr = sb + bufo + (uint32_t)(wm * 64 + mt * 16 + (lane & 15)) * 80 + colb;
                LDSM4(ah[mt], addr);
            }
#pragma unroll
            for (int pp = 0; pp < 2; pp++) {
                uint32_t addr = sb + bufo + 10240 + (uint32_t)(wn * 32 + pp * 16 + (lane & 15)) * 80 + colb;
                LDSM4(bh2[pp], addr);
            }
#pragma unroll
            for (int mt = 0; mt < 4; mt++)
#pragma unroll
                for (int nn = 0; nn < 4; nn++) {
                    int pp = nn >> 1, od = nn & 1;
                    MMA_BF16(c[mt][nn], ah[mt], bh2[pp][od], bh2[pp][2 + od]);
                }
        }
        __syncthreads();
    }

    float* nbs = (float*)sm;
    for (int q = tid; q < 128; q += 256)
        nbs[q] = (j0 + q < nc) ? d_norm[s * N_TOTAL + nt + j0 + q] : 0.0f;
    __syncthreads();

    int rsU = (nc + 16) & ~15;
    float lmax = 0.0f, lsum = 0.0f;
#pragma unroll
    for (int mt = 0; mt < 4; mt++) {
        int gi0 = i0 + wm * 64 + mt * 16 + (lane >> 2);
        int gi1 = gi0 + 8;
        float na0 = (gi0 < nt) ? d_norm[s * N_TOTAL + gi0] : 0.0f;
        float na1 = (gi1 < nt) ? d_norm[s * N_TOTAL + gi1] : 0.0f;
#pragma unroll
        for (int nn = 0; nn < 4; nn++) {
            int lj = wn * 32 + nn * 8 + (lane & 3) * 2;
            int gj = j0 + lj;
            float nb0 = nbs[lj], nb1 = nbs[lj + 1];
            bool vj0 = gj < nc, vj1 = (gj + 1) < nc;
            float m00 = na0 + nb0 - 2.0f * c[mt][nn][0];
            float m01 = na0 + nb1 - 2.0f * c[mt][nn][1];
            float m10 = na1 + nb0 - 2.0f * c[mt][nn][2];
            float m11 = na1 + nb1 - 2.0f * c[mt][nn][3];
            if (gi0 < nt) {
                __half* Mr = d_Mh + (size_t)s * PER_TS + (size_t)gi0 * rsU + gj;
                if (vj0) { lmax = fmaxf(lmax, m00); lsum += m00; }
                if (vj1) { lmax = fmaxf(lmax, m01); lsum += m01; }
                if (vj0 && vj1) *(__half2*)Mr = __floats2half2_rn(m00, m01);
                else if (vj0)   *Mr = __float2half_rn(m00);
            }
            if (gi1 < nt) {
                __half* Mr = d_Mh + (size_t)s * PER_TS + (size_t)gi1 * rsU + gj;
                if (vj0) { lmax = fmaxf(lmax, m10); lsum += m10; }
                if (vj1) { lmax = fmaxf(lmax, m11); lsum += m11; }
                if (vj0 && vj1) *(__half2*)Mr = __floats2half2_rn(m10, m11);
                else if (vj0)   *Mr = __float2half_rn(m10);
            }
        }
    }

    rbuf[tid] = lmax; __syncthreads();
    for (int st = 128; st; st >>= 1) {
        if (tid < st) rbuf[tid] = fmaxf(rbuf[tid], rbuf[tid + st]);
        __syncthreads();
    }
    if (tid == 0) d_pmax[pidx] = rbuf[0];
    __syncthreads();
    rbuf[tid] = lsum; __syncthreads();
    for (int st = 128; st; st >>= 1) {
        if (tid < st) rbuf[tid] += rbuf[tid + st];
        __syncthreads();
    }
    if (tid == 0) d_psum[pidx] = rbuf[0];
}

// ---------------- 4) per-timestep stats --------------------------------------
__global__ void reduce_stats() {
    __shared__ float rb[256];
    int s = blockIdx.x, tid = threadIdx.x;
    float mv = d_pmax[s * 256 + tid];
    float sv = d_psum[s * 256 + tid];
    rb[tid] = mv; __syncthreads();
    for (int st = 128; st; st >>= 1) {
        if (tid < st) rb[tid] = fmaxf(rb[tid], rb[tid + st]);
        __syncthreads();
    }
    float mx = rb[0];
    __syncthreads();
    rb[tid] = sv; __syncthreads();
    for (int st = 128; st; st >>= 1) {
        if (tid < st) rb[tid] += rb[tid + st];
        __syncthreads();
    }
    if (tid == 0) {
        d_delta[s] = mx;
        d_lam[s] = ((float)d_nt * (float)d_nc) / rb[0];
    }
}

// ---------------- 5) persistent Sinkhorn: 32 clusters of 8 CTAs, 512 thr -----
// smem-staged vector operands: u for colpass, z for rowpass/finalsum.
__device__ __forceinline__ void colpass_f(
    const __half* Kb, const float* ub, float* zb, float (*red)[164], float* svec,
    int ntp, int nc, int rsU, int Wc, int cbase, int lane, int wid, int tid,
    float bn, float bp)
{
    // stage u into smem (one L2 pass)
    for (int i = tid; i < ntp; i += 512) svec[i] = __ldcg(ub + i);
    __syncthreads();

    float acc[2][4] = {{0.f,0.f,0.f,0.f},{0.f,0.f,0.f,0.f}};
    int l4 = lane * 4;
    int jj0 = cbase + l4;
    int jj1 = jj0 + 128;
    bool v0 = (l4 < Wc) && (jj0 < rsU);
    bool v1 = (l4 + 128 < Wc) && (jj1 < rsU);
#pragma unroll 8
    for (int i = wid; i < ntp; i += 16) {
        float u = svec[i];
        const __half* Kr = Kb + (size_t)i * rsU;
        if (v0) {
            float4 f = h4_f4(*(const uint2*)(Kr + jj0));
            acc[0][0] = fmaf(f.x, u, acc[0][0]);
            acc[0][1] = fmaf(f.y, u, acc[0][1]);
            acc[0][2] = fmaf(f.z, u, acc[0][2]);
            acc[0][3] = fmaf(f.w, u, acc[0][3]);
        }
        if (v1) {
            float4 f = h4_f4(*(const uint2*)(Kr + jj1));
            acc[1][0] = fmaf(f.x, u, acc[1][0]);
            acc[1][1] = fmaf(f.y, u, acc[1][1]);
            acc[1][2] = fmaf(f.z, u, acc[1][2]);
            acc[1][3] = fmaf(f.w, u, acc[1][3]);
        }
    }
    if (v0) {
#pragma unroll
        for (int q = 0; q < 4; q++) red[wid][l4 + q] = acc[0][q];
    }
    if (v1) {
#pragma unroll
        for (int q = 0; q < 4; q++) red[wid][128 + l4 + q] = acc[1][q];
    }
    __syncthreads();
    for (int cc = tid; cc < Wc; cc += 512) {
        int j = cbase + cc;
        if (j >= rsU) continue;
        float t = red[0][cc];
#pragma unroll
        for (int w = 1; w < 16; w++) t += red[w][cc];
        float zv = (j < nc) ? (bn / t) : ((j == nc) ? (bp / t) : 0.0f);
        __stcg(zb + j, zv);
    }
    __syncthreads();
}

__device__ __forceinline__ void rowpass_f(
    const __half* Kb, float* ub, const float* zb, float* svec,
    int r0, int r1, int nt, int rsU, int lane, int wid, int tid, float an, float ap)
{
    // stage z into smem (one L2 pass)
    for (int i = tid; i < rsU; i += 512) svec[i] = __ldcg(zb + i);
    __syncthreads();

    for (int i = r0 + wid; i < r1; i += 32) {
        int i2 = i + 16;
        bool has2 = i2 < r1;
        const __half* Kr1 = Kb + (size_t)i * rsU;
        const __half* Kr2 = Kb + (size_t)(has2 ? i2 : i) * rsU;
        float a1 = 0.0f, a2 = 0.0f;
#pragma unroll 4
        for (int jj = lane * 4; jj < rsU; jj += 128) {
            float4 zv = *(const float4*)(svec + jj);
            float4 k1 = h4_f4(*(const uint2*)(Kr1 + jj));
            float4 k2 = h4_f4(*(const uint2*)(Kr2 + jj));
            a1 = fmaf(k1.x, zv.x, a1); a1 = fmaf(k1.y, zv.y, a1);
            a1 = fmaf(k1.z, zv.z, a1); a1 = fmaf(k1.w, zv.w, a1);
            a2 = fmaf(k2.x, zv.x, a2); a2 = fmaf(k2.y, zv.y, a2);
            a2 = fmaf(k2.z, zv.z, a2); a2 = fmaf(k2.w, zv.w, a2);
        }
#pragma unroll
        for (int o = 16; o; o >>= 1) {
            a1 += __shfl_down_sync(0xffffffffu, a1, o);
            a2 += __shfl_down_sync(0xffffffffu, a2, o);
        }
        if (lane == 0) {
            __stcg(ub + i, ((i < nt) ? an : ap) / a1);
            if (has2) __stcg(ub + i2, ((i2 < nt) ? an : ap) / a2);
        }
    }
    __syncthreads();
}

__global__ void __cluster_dims__(8, 1, 1) __launch_bounds__(512, 2) sink_cluster() {
    __shared__ float red[16][164];
    __shared__ float wsum[16];
    __shared__ __align__(16) float svec[2064];
    int bid = blockIdx.x;
    int s = bid >> 3, cr = bid & 7;
    int tid = threadIdx.x, lane = tid & 31, wid = tid >> 5;
    int nt = d_nt, nc = d_nc, ntp = nt + 1;
    int rsU = (nc + 16) & ~15;
    float lam = d_lam[s], delta = d_delta[s], p = d_p;
    float an = p / (float)nt, ap = 1.0f - p;
    float bn = (1.0f - p) / (float)nc, bp = p;
    __half* Mb = d_Mh + (size_t)s * PER_TS;
    __half* Kb = d_Kh + (size_t)s * PER_TS;
    float* ub = d_u + s * ZSTRIDE;
    float* zb = d_z + s * ZSTRIDE;

    // ---- Phase A: build K fp16 + M pads on row slice; init u slice ----
    int H = (ntp + 7) >> 3;
    int r0 = cr * H;
    int r1 = min(ntp, r0 + H);
    float kpad = fexpf_(-lam * delta) + 1e-6f;
    float kcorner = 1.0f + 1e-6f;
    for (int r = r0; r < r1; r++) {
        __half* Mw = Mb + (size_t)r * rsU;
        __half* Kr = Kb + (size_t)r * rsU;
        for (int c = tid * 2; c < rsU; c += 1024) {
            float kk[2];
#pragma unroll
            for (int q = 0; q < 2; q++) {
                int cc = c + q;
                float kv;
                if (r < nt) {
                    if (cc < nc) {
                        kv = fexpf_(-lam * __half2float(Mw[cc])) + 1e-6f;
                    } else if (cc == nc) {
                        kv = kpad; Mw[cc] = __float2half_rn(delta);
                    } else {
                        kv = 0.0f; Mw[cc] = __float2half_rn(0.0f);
                    }
                } else {
                    if (cc < nc) { kv = kpad; Mw[cc] = __float2half_rn(delta); }
                    else if (cc == nc) { kv = kcorner; Mw[cc] = __float2half_rn(0.0f); }
                    else { kv = 0.0f; Mw[cc] = __float2half_rn(0.0f); }
                }
                kk[q] = kv;
            }
            __half2 h2 = __floats2half2_rn(kk[0], kk[1]);
            *(unsigned*)(Kr + c) = *(unsigned*)&h2;
        }
    }
    for (int i = r0 + tid; i < r1; i += 512) __stcg(ub + i, (i < nt) ? an : ap);
    CLUSTER_SYNC();

    // ---- Sinkhorn: 20 x (colpass, rowpass) + final colpass (v) ----
    int Wc = ((rsU >> 3) + 3) & ~3;
    int cbase = cr * Wc;
    for (int it = 0; it < 21; it++) {
        colpass_f(Kb, ub, zb, red, svec, ntp, nc, rsU, Wc, cbase, lane, wid, tid, bn, bp);
        CLUSTER_SYNC();
        if (it == 20) break;
        rowpass_f(Kb, ub, zb, svec, r0, r1, nt, rsU, lane, wid, tid, an, ap);
        CLUSTER_SYNC();
    }

    // ---- finalsum on row slice: sum_i u_i * sum_j K_ij M_ij z_j ----
    // stage v(=z) into smem
    for (int i = tid; i < rsU; i += 512) svec[i] = __ldcg(zb + i);
    __syncthreads();

    float part = 0.0f;
    for (int i = r0 + wid; i < r1; i += 32) {
        int i2 = i + 16;
        bool has2 = i2 < r1;
        const __half* Kr1 = Kb + (size_t)i * rsU;
        const __half* Mr1 = Mb + (size_t)i * rsU;
        const __half* Kr2 = Kb + (size_t)(has2 ? i2 : i) * rsU;
        const __half* Mr2 = Mb + (size_t)(has2 ? i2 : i) * rsU;
        float a1 = 0.0f, a2 = 0.0f;
#pragma unroll 2
        for (int jj = lane * 4; jj < rsU; jj += 128) {
            float4 zv = *(const float4*)(svec + jj);
            float4 k1 = h4_f4(*(const uint2*)(Kr1 + jj));
            float4 m1 = h4_f4(*(const uint2*)(Mr1 + jj));
            float4 k2 = h4_f4(*(const uint2*)(Kr2 + jj));
            float4 m2 = h4_f4(*(const uint2*)(Mr2 + jj));
            a1 = fmaf(k1.x * m1.x, zv.x, a1); a1 = fmaf(k1.y * m1.y, zv.y, a1);
            a1 = fmaf(k1.z * m1.z, zv.z, a1); a1 = fmaf(k1.w * m1.w, zv.w, a1);
            a2 = fmaf(k2.x * m2.x, zv.x, a2); a2 = fmaf(k2.y * m2.y, zv.y, a2);
            a2 = fmaf(k2.z * m2.z, zv.z, a2); a2 = fmaf(k2.w * m2.w, zv.w, a2);
        }
#pragma unroll
        for (int o = 16; o; o >>= 1) {
            a1 += __shfl_down_sync(0xffffffffu, a1, o);
            a2 += __shfl_down_sync(0xffffffffu, a2, o);
        }
        if (lane == 0) {
            part = fmaf(__ldcg(ub + i), a1, part);
            if (has2) part = fmaf(__ldcg(ub + i2), a2, part);
        }
    }
    if (lane == 0) wsum[wid] = part;
    __syncthreads();
    if (tid == 0) {
        float t = 0.0f;
#pragma unroll
        for (int w = 0; w < 16; w++) t += wsum[w];
        d_pfin[bid] = t;
    }
}

// ---------------- 6) final deterministic reduce ------------------------------
__global__ void finalreduce(float* __restrict__ out) {
    __shared__ float rb[256];
    int tid = threadIdx.x;
    rb[tid] = d_pfin[tid];
    __syncthreads();
    for (int st = 128; st; st >>= 1) {
        if (tid < st) rb[tid] += rb[tid + st];
        __syncthreads();
    }
    if (tid == 0) out[0] = 2.0f * rb[0];
}

// ---------------- launch -----------------------------------------------------
extern "C" void kernel_launch(void* const* d_in, const int* in_sizes, int n_in,
                              void* d_out, int out_size) {
    const float* enc = (const float*)d_in[0];
    const int*   t   = (const int*)d_in[2];
    float* out = (float*)d_out;

    part_kernel<<<1, 1024>>>(t);
    gather_kernel<<<dim3(N_TOTAL, S_STEPS), 64>>>(enc);
    gemm_kernel<<<dim3(16, 16, S_STEPS), 256>>>();
    reduce_stats<<<S_STEPS, 256>>>();
    sink_cluster<<<256, 512>>>();
    finalreduce<<<1, 256>>>(out);
}